// round 5
// baseline (speedup 1.0000x reference)
#include <cuda_runtime.h>
#include <cuda_fp16.h>
#include <cuda_bf16.h>
#include <cstdint>

// Problem constants (fixed by the reference)
#define NPTS   100000
#define C_IMG  512
#define C_PT   256
#define BSZ    8
#define IMH    48
#define IMW    160

#define TM     128               // points per CTA (MMA M)
#define NPANEL 16                // K panels of 32
#define W_CHUNK_BYTES 16384      // 256 n-rows x 32 k x 2B (swizzled, 64B rows)
#define S_PANEL_BYTES (TM * 64)  // 128 rows x 32 k x 2B (swizzled, 64B rows)

// dynamic smem layout
#define SM_WCACHE 0                          // float4[128] = 2048
#define SM_OCACHE 2048                       // int4[128]   = 2048
#define SM_S      4096                       // 2 x 8192
#define SM_WBUF   (4096 + 2 * S_PANEL_BYTES) // 2 x 16384
#define SMEM_FUSED (SM_WBUF + 2 * W_CHUNK_BYTES)   // 53248 B

// ---------------- scratch (device globals: no allocation allowed) -------------
__device__ __half g_imgT[BSZ * IMH * IMW * C_IMG];          // (B,H,W,C) fp16, ~63 MB
__device__ __align__(16) char g_Wbf16[C_PT * C_IMG * 2];    // bf16 W, chunked+swizzled
__device__ float  g_M[BSZ * 12];
__device__ float4 g_w[NPTS];
__device__ int4   g_off[NPTS];

// ---------------- helpers ------------------------------------------------------
__device__ __forceinline__ uint32_t smem_u32(const void* p) {
    uint32_t a;
    asm("{ .reg .u64 t; cvta.to.shared.u64 t, %1; cvt.u32.u64 %0, t; }"
        : "=r"(a) : "l"(p));
    return a;
}

#define LDSM_X4(r0, r1, r2, r3, addr) \
    asm volatile("ldmatrix.sync.aligned.m8n8.x4.shared.b16 {%0,%1,%2,%3}, [%4];" \
                 : "=r"(r0), "=r"(r1), "=r"(r2), "=r"(r3) : "r"(addr))

__device__ __forceinline__ void mma_bf16(float* d, const uint32_t* a,
                                         uint32_t b0, uint32_t b1) {
    asm volatile(
        "mma.sync.aligned.m16n8k16.row.col.f32.bf16.bf16.f32 "
        "{%0,%1,%2,%3}, {%4,%5,%6,%7}, {%8,%9}, {%0,%1,%2,%3};"
        : "+f"(d[0]), "+f"(d[1]), "+f"(d[2]), "+f"(d[3])
        : "r"(a[0]), "r"(a[1]), "r"(a[2]), "r"(a[3]), "r"(b0), "r"(b1));
}

#define CP_ASYNC16(dst, src) \
    asm volatile("cp.async.cg.shared.global [%0], [%1], 16;" \
                 :: "r"(dst), "l"(src) : "memory")
#define CP_COMMIT() asm volatile("cp.async.commit_group;" ::: "memory")
#define CP_WAIT_ALL() asm volatile("cp.async.wait_group 0;" ::: "memory")

// ================== kernel 0: combined projection matrices ===================
__global__ void build_mats_kernel(const float* __restrict__ P2,
                                  const float* __restrict__ R0,
                                  const float* __restrict__ Tr) {
    int b = threadIdx.x;
    if (b >= BSZ) return;
    float A[16];
    for (int i = 0; i < 4; ++i)
        for (int j = 0; j < 4; ++j) {
            float s = 0.f;
            for (int k = 0; k < 4; ++k)
                s += R0[b*16 + i*4 + k] * Tr[b*16 + k*4 + j];
            A[i*4 + j] = s;
        }
    for (int i = 0; i < 3; ++i)
        for (int j = 0; j < 4; ++j) {
            float s = 0.f;
            for (int k = 0; k < 4; ++k)
                s += P2[b*12 + i*4 + k] * A[k*4 + j];
            g_M[b*12 + i*4 + j] = s;
        }
}

// ================== kernel 1: transpose img (B,C,H,W)->(B,H,W,C) fp16 ========
__global__ void transpose_img_kernel(const float* __restrict__ img) {
    __shared__ float tile[32][33];
    int bz = blockIdx.z;
    int b = bz / IMH, y = bz % IMH;
    int x0 = blockIdx.x * 32, c0 = blockIdx.y * 32;
    int tx = threadIdx.x, ty = threadIdx.y;
    #pragma unroll
    for (int j = 0; j < 4; ++j) {
        int c = c0 + ty + j * 8;
        tile[ty + j * 8][tx] =
            img[((size_t)(b * C_IMG + c) * IMH + y) * IMW + x0 + tx];
    }
    __syncthreads();
    #pragma unroll
    for (int j = 0; j < 4; ++j) {
        int x = x0 + ty + j * 8;
        g_imgT[((size_t)((b * IMH + y) * IMW + x)) * C_IMG + c0 + tx] =
            __float2half(tile[tx][ty + j * 8]);
    }
}

// ================== kernel 2: per-point projection ============================
__global__ void project_kernel(const float* __restrict__ centers,
                               const int* __restrict__ bidx) {
    int tid = blockIdx.x * blockDim.x + threadIdx.x;
    if (tid >= NPTS) return;
    int b = bidx[tid];
    const float* M = g_M + b * 12;
    float x = centers[tid * 3 + 0];
    float y = centers[tid * 3 + 1];
    float z = centers[tid * 3 + 2];
    float u  = M[0] * x + M[1] * y + M[2]  * z + M[3];
    float v  = M[4] * x + M[5] * y + M[6]  * z + M[7];
    float zc = M[8] * x + M[9] * y + M[10] * z + M[11];
    float depth = fmaxf(zc, 1e-5f);
    float uu = u / depth;
    float vv = v / depth;
    bool valid = (zc > 0.f) && (uu >= 0.f) && (uu < (float)IMW) &&
                 (vv >= 0.f) && (vv < (float)IMH);
    float x0f = floorf(uu), y0f = floorf(vv);
    float wx1 = uu - x0f, wx0 = 1.f - wx1;
    float wy1 = vv - y0f, wy0 = 1.f - wy1;
    int xi0 = (int)x0f, yi0 = (int)y0f;

    int   xs[4] = {xi0, xi0 + 1, xi0, xi0 + 1};
    int   ys[4] = {yi0, yi0, yi0 + 1, yi0 + 1};
    float ws[4] = {wx0 * wy0, wx1 * wy0, wx0 * wy1, wx1 * wy1};
    float wo[4];
    int   oo[4];
    #pragma unroll
    for (int j = 0; j < 4; ++j) {
        bool inb = (xs[j] >= 0) && (xs[j] <= IMW - 1) &&
                   (ys[j] >= 0) && (ys[j] <= IMH - 1);
        int xc = min(max(xs[j], 0), IMW - 1);
        int yc = min(max(ys[j], 0), IMH - 1);
        oo[j] = ((b * IMH + yc) * IMW + xc) * C_IMG;
        wo[j] = (valid && inb) ? ws[j] : 0.f;   // select, never multiply (NaN safety)
    }
    g_w[tid]   = make_float4(wo[0], wo[1], wo[2], wo[3]);
    g_off[tid] = make_int4(oo[0], oo[1], oo[2], oo[3]);
}

// ================== kernel 3: align_w fp32 -> bf16, chunked + swizzled ========
// layout: chunk c (16KB, K=32): n-row (64B = 4 16B-blocks), block kb stored at
//         byte = c*16384 + n*64 + ((kb ^ ((n>>1)&3)) << 4)
__global__ void prep_w_kernel(const float* __restrict__ aw) {
    int idx = blockIdx.x * 256 + threadIdx.x;   // 16384 16B-blocks
    int n   = idx >> 6;          // out channel 0..255
    int kbg = idx & 63;          // global 16B k-block (8 bf16)
    int c   = kbg >> 2;          // chunk 0..15
    int kb  = kbg & 3;           // block within chunk
    const float4* src = (const float4*)&aw[(size_t)n * C_IMG + kbg * 8];
    float4 v0 = src[0];
    float4 v1 = src[1];
    uint32_t u[4];
    __nv_bfloat162 t0 = __float22bfloat162_rn(make_float2(v0.x, v0.y));
    __nv_bfloat162 t1 = __float22bfloat162_rn(make_float2(v0.z, v0.w));
    __nv_bfloat162 t2 = __float22bfloat162_rn(make_float2(v1.x, v1.y));
    __nv_bfloat162 t3 = __float22bfloat162_rn(make_float2(v1.z, v1.w));
    u[0] = *(uint32_t*)&t0; u[1] = *(uint32_t*)&t1;
    u[2] = *(uint32_t*)&t2; u[3] = *(uint32_t*)&t3;
    *(int4*)(g_Wbf16 + c * W_CHUNK_BYTES + n * 64 + ((kb ^ ((n >> 1) & 3)) << 4)) =
        *(int4*)u;
}

// ================== kernel 4: fused gather + HMMA GEMM, K-panel pipelined =====
// 512 threads = 16 warps, warp grid 4(M) x 4(N). Warp tile 32x64.
// K processed in 16 panels of 32; gather(c+1) overlaps MMA(c) via double buffer.
__global__ void __launch_bounds__(512, 1)
fuse_kernel(const float* __restrict__ point_feat,
            const float* __restrict__ align_b,
            float* __restrict__ out) {
    extern __shared__ char sm[];
    uint32_t smb = smem_u32(sm);
    float4* wcache = (float4*)(sm + SM_WCACHE);
    int4*   ocache = (int4*)(sm + SM_OCACHE);

    const int t    = threadIdx.x;
    const int lane = t & 31;
    const int warp = t >> 5;
    const int p0   = blockIdx.x * TM;

    // point weights/offsets -> smem
    if (t < TM) {
        int p = p0 + t;
        float4 w = make_float4(0.f, 0.f, 0.f, 0.f);
        int4   o = make_int4(0, 0, 0, 0);
        if (p < NPTS) { w = g_w[p]; o = g_off[p]; }
        wcache[t] = w;
        ocache[t] = o;
    }
    // prefetch W panel 0
    {
        uint32_t dst = smb + SM_WBUF;
        CP_ASYNC16(dst + t * 16, g_Wbf16 + (size_t)t * 16);
        CP_ASYNC16(dst + (t + 512) * 16, g_Wbf16 + (size_t)(t + 512) * 16);
        CP_COMMIT();
    }
    __syncthreads();   // wcache/ocache visible

    const __half2* img2 = (const __half2*)g_imgT;
    const int q  = t & 15;        // channel-pair within panel (fixed)
    const int pb = t >> 4;        // base point 0..31 (handles pb, pb+32, +64, +96)

    // ---- gather panel 0 into S buf 0 ------------------------------------------
    {
        #pragma unroll
        for (int j = 0; j < 4; ++j) {
            int p = pb + 32 * j;
            int4   o = ocache[p];
            float4 w = wcache[p];
            float2 f0 = __half22float2(img2[(o.x >> 1) + q]);
            float2 f1 = __half22float2(img2[(o.y >> 1) + q]);
            float2 f2 = __half22float2(img2[(o.z >> 1) + q]);
            float2 f3 = __half22float2(img2[(o.w >> 1) + q]);
            float se = w.x * f0.x + w.y * f1.x + w.z * f2.x + w.w * f3.x;
            float so = w.x * f0.y + w.y * f1.y + w.z * f2.y + w.w * f3.y;
            __nv_bfloat162 b2 = __float22bfloat162_rn(make_float2(se, so));
            uint32_t addr = smb + SM_S + p * 64 +
                            ((((unsigned)q >> 2) ^ ((p >> 1) & 3)) << 4) + (q & 3) * 4;
            asm volatile("st.shared.b32 [%0], %1;" :: "r"(addr), "r"(*(uint32_t*)&b2));
        }
    }
    CP_WAIT_ALL();
    __syncthreads();   // S0 + W0 ready

    // ---- mainloop ---------------------------------------------------------------
    const int wm = warp & 3;    // M group (32 rows)
    const int wn = warp >> 2;   // N group (64 cols)
    float acc[2][8][4];
    #pragma unroll
    for (int i = 0; i < 2; ++i)
        #pragma unroll
        for (int j = 0; j < 8; ++j)
            #pragma unroll
            for (int r = 0; r < 4; ++r) acc[i][j][r] = 0.f;

    const int arow0 = wm * 32 + (lane & 15);
    const int ahalf = lane >> 4;
    const int brow  = wn * 64 + (lane >> 4) * 8 + (lane & 7);
    const int bhalf = (lane >> 3) & 1;

    for (int c = 0; c < NPANEL; ++c) {
        const uint32_t scur = smb + SM_S    + (c & 1) * S_PANEL_BYTES;
        const uint32_t wcur = smb + SM_WBUF + (c & 1) * W_CHUNK_BYTES;

        // stage 1: issue gather LDGs for panel c+1 (latency hidden by MMA below)
        uint32_t g[16];
        if (c + 1 < NPANEL) {
            const int coff = (c + 1) * 16 + q;
            #pragma unroll
            for (int j = 0; j < 4; ++j) {
                int4 o = ocache[pb + 32 * j];
                g[j * 4 + 0] = *(const uint32_t*)(img2 + (o.x >> 1) + coff);
                g[j * 4 + 1] = *(const uint32_t*)(img2 + (o.y >> 1) + coff);
                g[j * 4 + 2] = *(const uint32_t*)(img2 + (o.z >> 1) + coff);
                g[j * 4 + 3] = *(const uint32_t*)(img2 + (o.w >> 1) + coff);
            }
            const char* src = g_Wbf16 + (size_t)(c + 1) * W_CHUNK_BYTES;
            uint32_t dst = smb + SM_WBUF + ((c + 1) & 1) * W_CHUNK_BYTES;
            CP_ASYNC16(dst + t * 16, src + (size_t)t * 16);
            CP_ASYNC16(dst + (t + 512) * 16, src + (size_t)(t + 512) * 16);
            CP_COMMIT();
        }

        // stage 2: MMA on panel c
        #pragma unroll
        for (int ks = 0; ks < 2; ++ks) {
            uint32_t a[2][4];
            #pragma unroll
            for (int i = 0; i < 2; ++i) {
                int row = arow0 + i * 16;
                int kb  = (ks * 2 + ahalf) ^ ((row >> 1) & 3);
                LDSM_X4(a[i][0], a[i][1], a[i][2], a[i][3],
                        scur + row * 64 + (kb << 4));
            }
            #pragma unroll
            for (int jj = 0; jj < 4; ++jj) {
                uint32_t b0, b1, b2, b3;
                int nrow = brow + jj * 16;
                int kb   = (ks * 2 + bhalf) ^ ((nrow >> 1) & 3);
                LDSM_X4(b0, b1, b2, b3, wcur + nrow * 64 + (kb << 4));
                mma_bf16(acc[0][2 * jj],     a[0], b0, b1);
                mma_bf16(acc[0][2 * jj + 1], a[0], b2, b3);
                mma_bf16(acc[1][2 * jj],     a[1], b0, b1);
                mma_bf16(acc[1][2 * jj + 1], a[1], b2, b3);
            }
        }

        // stage 3: blend + store panel c+1 into the other S buffer
        if (c + 1 < NPANEL) {
            uint32_t snxt = smb + SM_S + ((c + 1) & 1) * S_PANEL_BYTES;
            #pragma unroll
            for (int j = 0; j < 4; ++j) {
                int p = pb + 32 * j;
                float4 w = wcache[p];
                float2 f0 = __half22float2(*(const __half2*)&g[j * 4 + 0]);
                float2 f1 = __half22float2(*(const __half2*)&g[j * 4 + 1]);
                float2 f2 = __half22float2(*(const __half2*)&g[j * 4 + 2]);
                float2 f3 = __half22float2(*(const __half2*)&g[j * 4 + 3]);
                float se = w.x * f0.x + w.y * f1.x + w.z * f2.x + w.w * f3.x;
                float so = w.x * f0.y + w.y * f1.y + w.z * f2.y + w.w * f3.y;
                __nv_bfloat162 b2 = __float22bfloat162_rn(make_float2(se, so));
                uint32_t addr = snxt + p * 64 +
                                ((((unsigned)q >> 2) ^ ((p >> 1) & 3)) << 4) + (q & 3) * 4;
                asm volatile("st.shared.b32 [%0], %1;" :: "r"(addr), "r"(*(uint32_t*)&b2));
            }
            CP_WAIT_ALL();
        }
        __syncthreads();
    }

    // ---- epilogue: out = point_feat + bias + acc -------------------------------
    const int cbase = wn * 64 + (lane & 3) * 2;
    float2 bias[8];
    #pragma unroll
    for (int j = 0; j < 8; ++j)
        bias[j] = *(const float2*)&align_b[cbase + j * 8];

    const int rbase = p0 + wm * 32 + (lane >> 2);
    #pragma unroll
    for (int i = 0; i < 2; ++i) {
        #pragma unroll
        for (int half = 0; half < 2; ++half) {
            int row = rbase + i * 16 + half * 8;
            if (row < NPTS) {
                #pragma unroll
                for (int j = 0; j < 8; ++j) {
                    int col = cbase + j * 8;
                    float2 a = *(const float2*)&point_feat[(size_t)row * C_PT + col];
                    float2 o;
                    o.x = a.x + bias[j].x + acc[i][j][half * 2 + 0];
                    o.y = a.y + bias[j].y + acc[i][j][half * 2 + 1];
                    *(float2*)&out[(size_t)row * C_PT + col] = o;
                }
            }
        }
    }
}

// ================== launcher ==================================================
extern "C" void kernel_launch(void* const* d_in, const int* in_sizes, int n_in,
                              void* d_out, int out_size) {
    const float* point_feat = (const float*)d_in[0];
    const float* centers    = (const float*)d_in[1];
    const float* img        = (const float*)d_in[2];
    const float* P2         = (const float*)d_in[3];
    const float* R0         = (const float*)d_in[4];
    const float* Tr         = (const float*)d_in[5];
    const float* align_w    = (const float*)d_in[6];
    const float* align_b    = (const float*)d_in[7];
    const int*   bidx       = (const int*)d_in[8];
    float* out = (float*)d_out;

    build_mats_kernel<<<1, 32>>>(P2, R0, Tr);
    transpose_img_kernel<<<dim3(IMW / 32, C_IMG / 32, BSZ * IMH), dim3(32, 8)>>>(img);
    project_kernel<<<(NPTS + 255) / 256, 256>>>(centers, bidx);
    prep_w_kernel<<<64, 256>>>(align_w);

    cudaFuncSetAttribute(fuse_kernel,
                         cudaFuncAttributeMaxDynamicSharedMemorySize, SMEM_FUSED);
    fuse_kernel<<<(NPTS + TM - 1) / TM, 512, SMEM_FUSED>>>(point_feat, align_b, out);
}

// round 6
// speedup vs baseline: 1.2565x; 1.2565x over previous
#include <cuda_runtime.h>
#include <cuda_fp16.h>
#include <cuda_bf16.h>
#include <cstdint>

// Problem constants (fixed by the reference)
#define NPTS   100000
#define C_IMG  512
#define C_PT   256
#define BSZ    8
#define IMH    48
#define IMW    160

#define TM     64                // points per CTA (MMA M)
#define NCHUNK 16                // K chunks of 32
#define W_CHUNK_BYTES 16384      // 256 n-rows x 32 k x 2B (swizzled, 64B rows)
#define S_BYTES (TM * 1024)      // 64 rows x 512 k x 2B (swizzled, 1KB rows)

// dynamic smem layout
#define SM_WCACHE 0                         // float4[64] = 1024
#define SM_OCACHE 1024                      // int4[64]   = 1024
#define SM_S      2048
#define SM_WBUF   (2048 + S_BYTES)          // 2 x 16384
#define SMEM_FUSED (SM_WBUF + 2 * W_CHUNK_BYTES)   // 100352 B -> 2 CTAs/SM

#define TRANSPOSE_BLOCKS (5 * 16 * 384)     // (W/32) * (C/32) * (B*H)

// ---------------- scratch (device globals: no allocation allowed) -------------
__device__ __half g_imgT[BSZ * IMH * IMW * C_IMG];          // (B,H,W,C) fp16, ~63 MB
__device__ __align__(16) char g_Wbf16[C_PT * C_IMG * 2];    // bf16 W, chunked+swizzled
__device__ float  g_M[BSZ * 12];
__device__ float4 g_w[NPTS];
__device__ int4   g_off[NPTS];

// ---------------- helpers ------------------------------------------------------
__device__ __forceinline__ uint32_t smem_u32(const void* p) {
    uint32_t a;
    asm("{ .reg .u64 t; cvta.to.shared.u64 t, %1; cvt.u32.u64 %0, t; }"
        : "=r"(a) : "l"(p));
    return a;
}

#define LDSM_X4(r0, r1, r2, r3, addr) \
    asm volatile("ldmatrix.sync.aligned.m8n8.x4.shared.b16 {%0,%1,%2,%3}, [%4];" \
                 : "=r"(r0), "=r"(r1), "=r"(r2), "=r"(r3) : "r"(addr))

__device__ __forceinline__ void mma_bf16(float* d, const uint32_t* a,
                                         uint32_t b0, uint32_t b1) {
    asm volatile(
        "mma.sync.aligned.m16n8k16.row.col.f32.bf16.bf16.f32 "
        "{%0,%1,%2,%3}, {%4,%5,%6,%7}, {%8,%9}, {%0,%1,%2,%3};"
        : "+f"(d[0]), "+f"(d[1]), "+f"(d[2]), "+f"(d[3])
        : "r"(a[0]), "r"(a[1]), "r"(a[2]), "r"(a[3]), "r"(b0), "r"(b1));
}

#define CP_ASYNC16(dst, src) \
    asm volatile("cp.async.cg.shared.global [%0], [%1], 16;" \
                 :: "r"(dst), "l"(src) : "memory")
#define CP_COMMIT() asm volatile("cp.async.commit_group;" ::: "memory")
#define CP_WAIT_ALL() asm volatile("cp.async.wait_group 0;" ::: "memory")

// ================== kernel 0: combined projection matrices ===================
__global__ void build_mats_kernel(const float* __restrict__ P2,
                                  const float* __restrict__ R0,
                                  const float* __restrict__ Tr) {
    int b = threadIdx.x;
    if (b >= BSZ) return;
    float A[16];
    for (int i = 0; i < 4; ++i)
        for (int j = 0; j < 4; ++j) {
            float s = 0.f;
            for (int k = 0; k < 4; ++k)
                s += R0[b*16 + i*4 + k] * Tr[b*16 + k*4 + j];
            A[i*4 + j] = s;
        }
    for (int i = 0; i < 3; ++i)
        for (int j = 0; j < 4; ++j) {
            float s = 0.f;
            for (int k = 0; k < 4; ++k)
                s += P2[b*12 + i*4 + k] * A[k*4 + j];
            g_M[b*12 + i*4 + j] = s;
        }
}

// ================== kernel 1: transpose img + convert W (merged dispatch) =====
// blocks [0, TRANSPOSE_BLOCKS): img (B,C,H,W) -> (B,H,W,C) fp16
// blocks [TRANSPOSE_BLOCKS, +64): align_w fp32 -> bf16 chunked+swizzled
__global__ void prep_kernel(const float* __restrict__ img,
                            const float* __restrict__ aw) {
    __shared__ float tile[32][33];
    const int t = threadIdx.x;
    if (blockIdx.x < TRANSPOSE_BLOCKS) {
        int blk = blockIdx.x;
        int bx = blk % 5;              // W/32
        int by = (blk / 5) % 16;       // C/32
        int bz = blk / (5 * 16);       // B*H
        int b = bz / IMH, y = bz % IMH;
        int x0 = bx * 32, c0 = by * 32;
        int tx = t & 31, ty = t >> 5;
        #pragma unroll
        for (int j = 0; j < 4; ++j) {
            int c = c0 + ty + j * 8;
            tile[ty + j * 8][tx] =
                img[((size_t)(b * C_IMG + c) * IMH + y) * IMW + x0 + tx];
        }
        __syncthreads();
        #pragma unroll
        for (int j = 0; j < 4; ++j) {
            int x = x0 + ty + j * 8;
            g_imgT[((size_t)((b * IMH + y) * IMW + x)) * C_IMG + c0 + tx] =
                __float2half(tile[tx][ty + j * 8]);
        }
    } else {
        // W conversion: chunk c (16KB, K=32): n-row 64B = 4 16B-blocks,
        // block kb at byte c*16384 + n*64 + ((kb ^ ((n>>1)&3)) << 4)
        int idx = (blockIdx.x - TRANSPOSE_BLOCKS) * 256 + t;   // 16384 blocks
        int n   = idx >> 6;
        int kbg = idx & 63;
        int c   = kbg >> 2;
        int kb  = kbg & 3;
        const float4* src = (const float4*)&aw[(size_t)n * C_IMG + kbg * 8];
        float4 v0 = src[0];
        float4 v1 = src[1];
        uint32_t u[4];
        __nv_bfloat162 t0 = __float22bfloat162_rn(make_float2(v0.x, v0.y));
        __nv_bfloat162 t1 = __float22bfloat162_rn(make_float2(v0.z, v0.w));
        __nv_bfloat162 t2 = __float22bfloat162_rn(make_float2(v1.x, v1.y));
        __nv_bfloat162 t3 = __float22bfloat162_rn(make_float2(v1.z, v1.w));
        u[0] = *(uint32_t*)&t0; u[1] = *(uint32_t*)&t1;
        u[2] = *(uint32_t*)&t2; u[3] = *(uint32_t*)&t3;
        *(int4*)(g_Wbf16 + c * W_CHUNK_BYTES + n * 64 + ((kb ^ ((n >> 1) & 3)) << 4)) =
            *(int4*)u;
    }
}

// ================== kernel 2: per-point projection ============================
__global__ void project_kernel(const float* __restrict__ centers,
                               const int* __restrict__ bidx) {
    int tid = blockIdx.x * blockDim.x + threadIdx.x;
    if (tid >= NPTS) return;
    int b = bidx[tid];
    const float* M = g_M + b * 12;
    float x = centers[tid * 3 + 0];
    float y = centers[tid * 3 + 1];
    float z = centers[tid * 3 + 2];
    float u  = M[0] * x + M[1] * y + M[2]  * z + M[3];
    float v  = M[4] * x + M[5] * y + M[6]  * z + M[7];
    float zc = M[8] * x + M[9] * y + M[10] * z + M[11];
    float depth = fmaxf(zc, 1e-5f);
    float uu = u / depth;
    float vv = v / depth;
    bool valid = (zc > 0.f) && (uu >= 0.f) && (uu < (float)IMW) &&
                 (vv >= 0.f) && (vv < (float)IMH);
    float x0f = floorf(uu), y0f = floorf(vv);
    float wx1 = uu - x0f, wx0 = 1.f - wx1;
    float wy1 = vv - y0f, wy0 = 1.f - wy1;
    int xi0 = (int)x0f, yi0 = (int)y0f;

    int   xs[4] = {xi0, xi0 + 1, xi0, xi0 + 1};
    int   ys[4] = {yi0, yi0, yi0 + 1, yi0 + 1};
    float ws[4] = {wx0 * wy0, wx1 * wy0, wx0 * wy1, wx1 * wy1};
    float wo[4];
    int   oo[4];
    #pragma unroll
    for (int j = 0; j < 4; ++j) {
        bool inb = (xs[j] >= 0) && (xs[j] <= IMW - 1) &&
                   (ys[j] >= 0) && (ys[j] <= IMH - 1);
        int xc = min(max(xs[j], 0), IMW - 1);
        int yc = min(max(ys[j], 0), IMH - 1);
        oo[j] = ((b * IMH + yc) * IMW + xc) * C_IMG;
        wo[j] = (valid && inb) ? ws[j] : 0.f;   // select, never multiply (NaN safety)
    }
    g_w[tid]   = make_float4(wo[0], wo[1], wo[2], wo[3]);
    g_off[tid] = make_int4(oo[0], oo[1], oo[2], oo[3]);
}

// ================== kernel 3: fused gather + HMMA GEMM + residual =============
// 512 threads = 16 warps, warp grid 2(M) x 8(N). Warp tile 32x32.
// 98KB smem -> 2 CTAs/SM: gather/MMA/epilogue of co-resident CTAs overlap.
__global__ void __launch_bounds__(512, 2)
fuse_kernel(const float* __restrict__ point_feat,
            const float* __restrict__ align_b,
            float* __restrict__ out) {
    extern __shared__ char sm[];
    uint32_t smb = smem_u32(sm);
    float4* wcache = (float4*)(sm + SM_WCACHE);
    int4*   ocache = (int4*)(sm + SM_OCACHE);

    const int t    = threadIdx.x;
    const int lane = t & 31;
    const int warp = t >> 5;
    const int p0   = blockIdx.x * TM;

    // point weights/offsets -> smem
    if (t < TM) {
        int p = p0 + t;
        float4 w = make_float4(0.f, 0.f, 0.f, 0.f);
        int4   o = make_int4(0, 0, 0, 0);
        if (p < NPTS) { w = g_w[p]; o = g_off[p]; }
        wcache[t] = w;
        ocache[t] = o;
    }

    // prefetch W chunk 0 (overlaps gather)
    {
        const char* src = g_Wbf16;
        uint32_t dst = smb + SM_WBUF;
        #pragma unroll
        for (int j = 0; j < 2; ++j)
            CP_ASYNC16(dst + (t + j * 512) * 16, src + (size_t)(t + j * 512) * 16);
        CP_COMMIT();
    }
    __syncthreads();

    // ---- gather: S[p][k] bf16, swizzled. Thread owns channel quad q (8B) for
    //      16 points. LDG.64 (coalesced: warp = one point, 256B per corner),
    //      HFMA2 blend, STS.64 (conflict-free under XOR swizzle).
    const uint2* img4 = (const uint2*)g_imgT;         // 8B = 4 halves
    const int q  = t & 127;                           // channel quad
    const int pg = t >> 7;                            // point group (16 pts)
    const uint32_t sbase = smb + SM_S;
    #pragma unroll 4
    for (int i = 0; i < 16; ++i) {
        int p = pg * 16 + i;
        float4 w = wcache[p];
        int4   o = ocache[p];
        __half2 wx = __floats2half2_rn(w.x, w.x);
        __half2 wy = __floats2half2_rn(w.y, w.y);
        __half2 wz = __floats2half2_rn(w.z, w.z);
        __half2 ww = __floats2half2_rn(w.w, w.w);
        uint2 d0 = img4[(o.x >> 2) + q];
        uint2 d1 = img4[(o.y >> 2) + q];
        uint2 d2 = img4[(o.z >> 2) + q];
        uint2 d3 = img4[(o.w >> 2) + q];
        __half2 accA = __hmul2(wx, *(__half2*)&d0.x);
        __half2 accB = __hmul2(wx, *(__half2*)&d0.y);
        accA = __hfma2(wy, *(__half2*)&d1.x, accA);
        accB = __hfma2(wy, *(__half2*)&d1.y, accB);
        accA = __hfma2(wz, *(__half2*)&d2.x, accA);
        accB = __hfma2(wz, *(__half2*)&d2.y, accB);
        accA = __hfma2(ww, *(__half2*)&d3.x, accA);
        accB = __hfma2(ww, *(__half2*)&d3.y, accB);
        __nv_bfloat162 bA = __float22bfloat162_rn(__half22float2(accA));
        __nv_bfloat162 bB = __float22bfloat162_rn(__half22float2(accB));
        uint32_t addr = sbase + p * 1024 +
                        ((((unsigned)q >> 1) ^ (p & 7)) << 4) + (q & 1) * 8;
        asm volatile("st.shared.v2.b32 [%0], {%1, %2};"
                     :: "r"(addr), "r"(*(uint32_t*)&bA), "r"(*(uint32_t*)&bB));
    }
    CP_WAIT_ALL();      // W chunk 0 resident
    __syncthreads();    // S tile complete

    // ---- HMMA mainloop --------------------------------------------------------
    const int wm = warp & 1;    // M group (32 rows)
    const int wn = warp >> 1;   // N group (32 cols)
    float acc[2][4][4];
    #pragma unroll
    for (int i = 0; i < 2; ++i)
        #pragma unroll
        for (int j = 0; j < 4; ++j)
            #pragma unroll
            for (int r = 0; r < 4; ++r) acc[i][j][r] = 0.f;

    // per-lane invariant address parts
    const int arow0 = wm * 32 + (lane & 15);
    const int ahalf = lane >> 4;
    const int brow  = wn * 32 + (lane >> 4) * 8 + (lane & 7);
    const int bhalf = (lane >> 3) & 1;

    for (int c = 0; c < NCHUNK; ++c) {
        if (c + 1 < NCHUNK) {
            const char* src = g_Wbf16 + (size_t)(c + 1) * W_CHUNK_BYTES;
            uint32_t dst = smb + SM_WBUF + ((c + 1) & 1) * W_CHUNK_BYTES;
            #pragma unroll
            for (int j = 0; j < 2; ++j)
                CP_ASYNC16(dst + (t + j * 512) * 16, src + (size_t)(t + j * 512) * 16);
            CP_COMMIT();
        }
        const uint32_t wbuf = smb + SM_WBUF + (c & 1) * W_CHUNK_BYTES;

        #pragma unroll
        for (int ks = 0; ks < 2; ++ks) {
            uint32_t a[2][4];
            #pragma unroll
            for (int i = 0; i < 2; ++i) {
                int row  = arow0 + i * 16;
                int kblk = (c * 4 + ks * 2 + ahalf) ^ (row & 7);
                uint32_t addr = sbase + row * 1024 + (kblk << 4);
                LDSM_X4(a[i][0], a[i][1], a[i][2], a[i][3], addr);
            }
            #pragma unroll
            for (int jj = 0; jj < 2; ++jj) {
                uint32_t b0, b1, b2, b3;
                int nrow = brow + jj * 16;
                int kb   = (ks * 2 + bhalf) ^ ((nrow >> 1) & 3);
                uint32_t addr = wbuf + nrow * 64 + (kb << 4);
                LDSM_X4(b0, b1, b2, b3, addr);
                mma_bf16(acc[0][2 * jj],     a[0], b0, b1);
                mma_bf16(acc[0][2 * jj + 1], a[0], b2, b3);
                mma_bf16(acc[1][2 * jj],     a[1], b0, b1);
                mma_bf16(acc[1][2 * jj + 1], a[1], b2, b3);
            }
        }
        CP_WAIT_ALL();
        __syncthreads();
    }

    // ---- epilogue: out = point_feat + bias + acc -------------------------------
    const int cbase = wn * 32 + (lane & 3) * 2;
    float2 bias[4];
    #pragma unroll
    for (int j = 0; j < 4; ++j)
        bias[j] = *(const float2*)&align_b[cbase + j * 8];

    const int rbase = p0 + wm * 32 + (lane >> 2);
    #pragma unroll
    for (int i = 0; i < 2; ++i) {
        #pragma unroll
        for (int half = 0; half < 2; ++half) {
            int row = rbase + i * 16 + half * 8;
            if (row < NPTS) {
                #pragma unroll
                for (int j = 0; j < 4; ++j) {
                    int col = cbase + j * 8;
                    float2 a = *(const float2*)&point_feat[(size_t)row * C_PT + col];
                    float2 o;
                    o.x = a.x + bias[j].x + acc[i][j][half * 2 + 0];
                    o.y = a.y + bias[j].y + acc[i][j][half * 2 + 1];
                    *(float2*)&out[(size_t)row * C_PT + col] = o;
                }
            }
        }
    }
}

// ================== launcher ==================================================
extern "C" void kernel_launch(void* const* d_in, const int* in_sizes, int n_in,
                              void* d_out, int out_size) {
    const float* point_feat = (const float*)d_in[0];
    const float* centers    = (const float*)d_in[1];
    const float* img        = (const float*)d_in[2];
    const float* P2         = (const float*)d_in[3];
    const float* R0         = (const float*)d_in[4];
    const float* Tr         = (const float*)d_in[5];
    const float* align_w    = (const float*)d_in[6];
    const float* align_b    = (const float*)d_in[7];
    const int*   bidx       = (const int*)d_in[8];
    float* out = (float*)d_out;

    build_mats_kernel<<<1, 32>>>(P2, R0, Tr);
    prep_kernel<<<TRANSPOSE_BLOCKS + 64, 256>>>(img, align_w);
    project_kernel<<<(NPTS + 255) / 256, 256>>>(centers, bidx);

    cudaFuncSetAttribute(fuse_kernel,
                         cudaFuncAttributeMaxDynamicSharedMemorySize, SMEM_FUSED);
    fuse_kernel<<<(NPTS + TM - 1) / TM, 512, SMEM_FUSED>>>(point_feat, align_b, out);
}

// round 7
// speedup vs baseline: 1.5475x; 1.2316x over previous
#include <cuda_runtime.h>
#include <cuda_fp16.h>
#include <cuda_bf16.h>
#include <cstdint>

// Problem constants (fixed by the reference)
#define NPTS   100000
#define C_IMG  512
#define C_PT   256
#define BSZ    8
#define IMH    48
#define IMW    160
#define NPIX   (BSZ * IMH * IMW)     // 61440

#define TM     64                // pixels per CTA (GEMM M tile)
#define NCHUNK 16                // K chunks of 32
#define W_CHUNK_BYTES 16384      // 256 n-rows x 32 k x 2B (swizzled, 64B rows)
#define A_CHUNK_BYTES 4096       // 64 rows x 32 k x 2B (swizzled, 64B rows)

// GEMM smem layout
#define SMG_A 0                               // 2 x 4096
#define SMG_W (2 * A_CHUNK_BYTES)             // 2 x 16384
#define SMEM_GEMM (SMG_W + 2 * W_CHUNK_BYTES) // 40960 B -> 2 CTAs/SM

#define TRANSPOSE_BLOCKS (5 * 16 * 384)       // (W/32) * (C/32) * (B*H)

// ---------------- scratch (device globals: no allocation allowed) -------------
__device__ __nv_bfloat16 g_imgTb[NPIX * C_IMG];             // (B,H,W,C) bf16, 63 MB
__device__ __align__(16) char g_Wbf16[C_PT * C_IMG * 2];    // bf16 W, chunked+swizzled
__device__ __align__(16) __half g_G[NPIX * C_PT];           // per-pixel aligned feat, 31.5 MB
__device__ float  g_M[BSZ * 12];
__device__ float4 g_w[NPTS];
__device__ int4   g_off[NPTS];

// ---------------- helpers ------------------------------------------------------
__device__ __forceinline__ uint32_t smem_u32(const void* p) {
    uint32_t a;
    asm("{ .reg .u64 t; cvta.to.shared.u64 t, %1; cvt.u32.u64 %0, t; }"
        : "=r"(a) : "l"(p));
    return a;
}

#define LDSM_X4(r0, r1, r2, r3, addr) \
    asm volatile("ldmatrix.sync.aligned.m8n8.x4.shared.b16 {%0,%1,%2,%3}, [%4];" \
                 : "=r"(r0), "=r"(r1), "=r"(r2), "=r"(r3) : "r"(addr))

__device__ __forceinline__ void mma_bf16(float* d, const uint32_t* a,
                                         uint32_t b0, uint32_t b1) {
    asm volatile(
        "mma.sync.aligned.m16n8k16.row.col.f32.bf16.bf16.f32 "
        "{%0,%1,%2,%3}, {%4,%5,%6,%7}, {%8,%9}, {%0,%1,%2,%3};"
        : "+f"(d[0]), "+f"(d[1]), "+f"(d[2]), "+f"(d[3])
        : "r"(a[0]), "r"(a[1]), "r"(a[2]), "r"(a[3]), "r"(b0), "r"(b1));
}

#define CP_ASYNC16(dst, src) \
    asm volatile("cp.async.cg.shared.global [%0], [%1], 16;" \
                 :: "r"(dst), "l"(src) : "memory")
#define CP_COMMIT() asm volatile("cp.async.commit_group;" ::: "memory")
#define CP_WAIT_ALL() asm volatile("cp.async.wait_group 0;" ::: "memory")

// ================== kernel 0: combined projection matrices ===================
__global__ void build_mats_kernel(const float* __restrict__ P2,
                                  const float* __restrict__ R0,
                                  const float* __restrict__ Tr) {
    int b = threadIdx.x;
    if (b >= BSZ) return;
    float A[16];
    for (int i = 0; i < 4; ++i)
        for (int j = 0; j < 4; ++j) {
            float s = 0.f;
            for (int k = 0; k < 4; ++k)
                s += R0[b*16 + i*4 + k] * Tr[b*16 + k*4 + j];
            A[i*4 + j] = s;
        }
    for (int i = 0; i < 3; ++i)
        for (int j = 0; j < 4; ++j) {
            float s = 0.f;
            for (int k = 0; k < 4; ++k)
                s += P2[b*12 + i*4 + k] * A[k*4 + j];
            g_M[b*12 + i*4 + j] = s;
        }
}

// ================== kernel 1: transpose img + convert W (merged dispatch) =====
__global__ void prep_kernel(const float* __restrict__ img,
                            const float* __restrict__ aw) {
    __shared__ float tile[32][33];
    const int t = threadIdx.x;
    if (blockIdx.x < TRANSPOSE_BLOCKS) {
        int blk = blockIdx.x;
        int bx = blk % 5;              // W/32
        int by = (blk / 5) % 16;       // C/32
        int bz = blk / (5 * 16);       // B*H
        int b = bz / IMH, y = bz % IMH;
        int x0 = bx * 32, c0 = by * 32;
        int tx = t & 31, ty = t >> 5;
        #pragma unroll
        for (int j = 0; j < 4; ++j) {
            int c = c0 + ty + j * 8;
            tile[ty + j * 8][tx] =
                img[((size_t)(b * C_IMG + c) * IMH + y) * IMW + x0 + tx];
        }
        __syncthreads();
        #pragma unroll
        for (int j = 0; j < 4; ++j) {
            int x = x0 + ty + j * 8;
            g_imgTb[((size_t)((b * IMH + y) * IMW + x)) * C_IMG + c0 + tx] =
                __float2bfloat16(tile[tx][ty + j * 8]);
        }
    } else {
        // W: chunk c (16KB, K=32): n-row 64B = 4 16B-blocks,
        // block kb at byte c*16384 + n*64 + ((kb ^ ((n>>1)&3)) << 4)
        int idx = (blockIdx.x - TRANSPOSE_BLOCKS) * 256 + t;
        int n   = idx >> 6;
        int kbg = idx & 63;
        int c   = kbg >> 2;
        int kb  = kbg & 3;
        const float4* src = (const float4*)&aw[(size_t)n * C_IMG + kbg * 8];
        float4 v0 = src[0];
        float4 v1 = src[1];
        uint32_t u[4];
        __nv_bfloat162 t0 = __float22bfloat162_rn(make_float2(v0.x, v0.y));
        __nv_bfloat162 t1 = __float22bfloat162_rn(make_float2(v0.z, v0.w));
        __nv_bfloat162 t2 = __float22bfloat162_rn(make_float2(v1.x, v1.y));
        __nv_bfloat162 t3 = __float22bfloat162_rn(make_float2(v1.z, v1.w));
        u[0] = *(uint32_t*)&t0; u[1] = *(uint32_t*)&t1;
        u[2] = *(uint32_t*)&t2; u[3] = *(uint32_t*)&t3;
        *(int4*)(g_Wbf16 + c * W_CHUNK_BYTES + n * 64 + ((kb ^ ((n >> 1) & 3)) << 4)) =
            *(int4*)u;
    }
}

// ================== kernel 2: per-point projection ============================
__global__ void project_kernel(const float* __restrict__ centers,
                               const int* __restrict__ bidx) {
    int tid = blockIdx.x * blockDim.x + threadIdx.x;
    if (tid >= NPTS) return;
    int b = bidx[tid];
    const float* M = g_M + b * 12;
    float x = centers[tid * 3 + 0];
    float y = centers[tid * 3 + 1];
    float z = centers[tid * 3 + 2];
    float u  = M[0] * x + M[1] * y + M[2]  * z + M[3];
    float v  = M[4] * x + M[5] * y + M[6]  * z + M[7];
    float zc = M[8] * x + M[9] * y + M[10] * z + M[11];
    float depth = fmaxf(zc, 1e-5f);
    float uu = u / depth;
    float vv = v / depth;
    bool valid = (zc > 0.f) && (uu >= 0.f) && (uu < (float)IMW) &&
                 (vv >= 0.f) && (vv < (float)IMH);
    float x0f = floorf(uu), y0f = floorf(vv);
    float wx1 = uu - x0f, wx0 = 1.f - wx1;
    float wy1 = vv - y0f, wy0 = 1.f - wy1;
    int xi0 = (int)x0f, yi0 = (int)y0f;

    int   xs[4] = {xi0, xi0 + 1, xi0, xi0 + 1};
    int   ys[4] = {yi0, yi0, yi0 + 1, yi0 + 1};
    float ws[4] = {wx0 * wy0, wx1 * wy0, wx0 * wy1, wx1 * wy1};
    float wo[4];
    int   oo[4];
    #pragma unroll
    for (int j = 0; j < 4; ++j) {
        bool inb = (xs[j] >= 0) && (xs[j] <= IMW - 1) &&
                   (ys[j] >= 0) && (ys[j] <= IMH - 1);
        int xc = min(max(xs[j], 0), IMW - 1);
        int yc = min(max(ys[j], 0), IMH - 1);
        oo[j] = ((b * IMH + yc) * IMW + xc) * C_PT;   // offsets into G (256/px)
        wo[j] = (valid && inb) ? ws[j] : 0.f;   // select, never multiply (NaN safety)
    }
    g_w[tid]   = make_float4(wo[0], wo[1], wo[2], wo[3]);
    g_off[tid] = make_int4(oo[0], oo[1], oo[2], oo[3]);
}

// ================== kernel 3: dense pixel GEMM  G = imgT @ W^T ================
// 512 threads = 16 warps, warp grid 2(M) x 8(N). Warp tile 32x32.
// M = 64 pixels/CTA (grid 960), N = 256, K = 512 in 16 cp.async-fed chunks.
__global__ void __launch_bounds__(512, 2)
gemm_kernel() {
    extern __shared__ char sm[];
    uint32_t smb = smem_u32(sm);

    const int t    = threadIdx.x;
    const int lane = t & 31;
    const int warp = t >> 5;
    const int p0   = blockIdx.x * TM;    // pixel base

    // prefetch chunk 0 (A + W)
    if (t < 256) {
        int pix = t >> 2, kb = t & 3;
        const char* src = (const char*)g_imgTb + (size_t)(p0 + pix) * 1024 + kb * 16;
        CP_ASYNC16(smb + SMG_A + pix * 64 + ((kb ^ ((pix >> 1) & 3)) << 4), src);
    }
    {
        const char* src = g_Wbf16;
        uint32_t dst = smb + SMG_W;
        CP_ASYNC16(dst + t * 16, src + (size_t)t * 16);
        CP_ASYNC16(dst + (t + 512) * 16, src + (size_t)(t + 512) * 16);
        CP_COMMIT();
    }

    const int wm = warp & 1;    // M group (32 rows)
    const int wn = warp >> 1;   // N group (32 cols)
    float acc[2][4][4];
    #pragma unroll
    for (int i = 0; i < 2; ++i)
        #pragma unroll
        for (int j = 0; j < 4; ++j)
            #pragma unroll
            for (int r = 0; r < 4; ++r) acc[i][j][r] = 0.f;

    const int arow0 = wm * 32 + (lane & 15);
    const int ahalf = lane >> 4;
    const int brow  = wn * 32 + (lane >> 4) * 8 + (lane & 7);
    const int bhalf = (lane >> 3) & 1;

    CP_WAIT_ALL();
    __syncthreads();

    for (int c = 0; c < NCHUNK; ++c) {
        if (c + 1 < NCHUNK) {
            if (t < 256) {
                int pix = t >> 2, kb = t & 3;
                const char* src = (const char*)g_imgTb +
                                  (size_t)(p0 + pix) * 1024 + (c + 1) * 64 + kb * 16;
                CP_ASYNC16(smb + SMG_A + ((c + 1) & 1) * A_CHUNK_BYTES +
                           pix * 64 + ((kb ^ ((pix >> 1) & 3)) << 4), src);
            }
            const char* src = g_Wbf16 + (size_t)(c + 1) * W_CHUNK_BYTES;
            uint32_t dst = smb + SMG_W + ((c + 1) & 1) * W_CHUNK_BYTES;
            CP_ASYNC16(dst + t * 16, src + (size_t)t * 16);
            CP_ASYNC16(dst + (t + 512) * 16, src + (size_t)(t + 512) * 16);
            CP_COMMIT();
        }
        const uint32_t abuf = smb + SMG_A + (c & 1) * A_CHUNK_BYTES;
        const uint32_t wbuf = smb + SMG_W + (c & 1) * W_CHUNK_BYTES;

        #pragma unroll
        for (int ks = 0; ks < 2; ++ks) {
            uint32_t a[2][4];
            #pragma unroll
            for (int i = 0; i < 2; ++i) {
                int row = arow0 + i * 16;
                int kb  = (ks * 2 + ahalf) ^ ((row >> 1) & 3);
                LDSM_X4(a[i][0], a[i][1], a[i][2], a[i][3],
                        abuf + row * 64 + (kb << 4));
            }
            #pragma unroll
            for (int jj = 0; jj < 2; ++jj) {
                uint32_t b0, b1, b2, b3;
                int nrow = brow + jj * 16;
                int kb   = (ks * 2 + bhalf) ^ ((nrow >> 1) & 3);
                LDSM_X4(b0, b1, b2, b3, wbuf + nrow * 64 + (kb << 4));
                mma_bf16(acc[0][2 * jj],     a[0], b0, b1);
                mma_bf16(acc[0][2 * jj + 1], a[0], b2, b3);
                mma_bf16(acc[1][2 * jj],     a[1], b0, b1);
                mma_bf16(acc[1][2 * jj + 1], a[1], b2, b3);
            }
        }
        CP_WAIT_ALL();
        __syncthreads();
    }

    // ---- epilogue: G[pixel][col] = acc (fp16) -----------------------------------
    const int cbase = wn * 32 + (lane & 3) * 2;
    const int rbase = p0 + wm * 32 + (lane >> 2);
    #pragma unroll
    for (int i = 0; i < 2; ++i) {
        #pragma unroll
        for (int half = 0; half < 2; ++half) {
            int pix = rbase + i * 16 + half * 8;
            #pragma unroll
            for (int j = 0; j < 4; ++j) {
                int col = cbase + j * 8;
                __half2 h = __floats2half2_rn(acc[i][j][half * 2 + 0],
                                              acc[i][j][half * 2 + 1]);
                *(__half2*)&g_G[(size_t)pix * C_PT + col] = h;
            }
        }
    }
}

// ================== kernel 4: per-point blend + residual ======================
// 1 warp per point; lane owns 8 channels. G is L2-resident (31.5 MB).
__global__ void __launch_bounds__(256)
blend_kernel(const float* __restrict__ point_feat,
             const float* __restrict__ align_b,
             float* __restrict__ out) {
    const int lane = threadIdx.x & 31;
    const int p    = blockIdx.x * 8 + (threadIdx.x >> 5);
    const int ch   = lane * 8;

    float4 w = g_w[p];
    int4   o = g_off[p];
    uint4 c0 = *(const uint4*)(g_G + o.x + ch);
    uint4 c1 = *(const uint4*)(g_G + o.y + ch);
    uint4 c2 = *(const uint4*)(g_G + o.z + ch);
    uint4 c3 = *(const uint4*)(g_G + o.w + ch);

    float acc[8];
    #pragma unroll
    for (int k = 0; k < 4; ++k) {
        float2 f0 = __half22float2(((const __half2*)&c0)[k]);
        float2 f1 = __half22float2(((const __half2*)&c1)[k]);
        float2 f2 = __half22float2(((const __half2*)&c2)[k]);
        float2 f3 = __half22float2(((const __half2*)&c3)[k]);
        acc[2*k+0] = w.x * f0.x + w.y * f1.x + w.z * f2.x + w.w * f3.x;
        acc[2*k+1] = w.x * f0.y + w.y * f1.y + w.z * f2.y + w.w * f3.y;
    }

    const float4* pf = (const float4*)&point_feat[(size_t)p * C_PT + ch];
    const float4* bb = (const float4*)&align_b[ch];
    float4* op = (float4*)&out[(size_t)p * C_PT + ch];
    #pragma unroll
    for (int k = 0; k < 2; ++k) {
        float4 a = pf[k];
        float4 b = bb[k];
        float4 r;
        r.x = a.x + b.x + acc[4*k+0];
        r.y = a.y + b.y + acc[4*k+1];
        r.z = a.z + b.z + acc[4*k+2];
        r.w = a.w + b.w + acc[4*k+3];
        op[k] = r;
    }
}

// ================== launcher ==================================================
extern "C" void kernel_launch(void* const* d_in, const int* in_sizes, int n_in,
                              void* d_out, int out_size) {
    const float* point_feat = (const float*)d_in[0];
    const float* centers    = (const float*)d_in[1];
    const float* img        = (const float*)d_in[2];
    const float* P2         = (const float*)d_in[3];
    const float* R0         = (const float*)d_in[4];
    const float* Tr         = (const float*)d_in[5];
    const float* align_w    = (const float*)d_in[6];
    const float* align_b    = (const float*)d_in[7];
    const int*   bidx       = (const int*)d_in[8];
    float* out = (float*)d_out;

    build_mats_kernel<<<1, 32>>>(P2, R0, Tr);
    prep_kernel<<<TRANSPOSE_BLOCKS + 64, 256>>>(img, align_w);
    project_kernel<<<(NPTS + 255) / 256, 256>>>(centers, bidx);

    cudaFuncSetAttribute(gemm_kernel,
                         cudaFuncAttributeMaxDynamicSharedMemorySize, SMEM_GEMM);
    gemm_kernel<<<NPIX / TM, 512, SMEM_GEMM>>>();
    blend_kernel<<<NPTS / 8, 256>>>(point_feat, align_b, out);
}

// round 8
// speedup vs baseline: 1.8048x; 1.1663x over previous
#include <cuda_runtime.h>
#include <cuda_fp16.h>
#include <cuda_bf16.h>
#include <cstdint>

// Problem constants (fixed by the reference)
#define NPTS   100000
#define C_IMG  512
#define C_PT   256
#define BSZ    8
#define IMH    48
#define IMW    160
#define NPIX   (BSZ * IMH * IMW)     // 61440
#define PIXB   (IMH * IMW)           // 7680 pixels per batch

#define TM     64                // pixels per CTA (GEMM M tile)
#define NCHUNK 16                // K chunks of 32
#define W_CHUNK_BYTES 16384      // 256 n-rows x 32 k x 2B (swizzled, 64B rows)
#define A_CHUNK_BYTES 4096       // 32 k-rows x 64 pix x 2B (swizzled, 128B rows)

// GEMM smem layout
#define SMG_A 0                               // 2 x 4096
#define SMG_W (2 * A_CHUNK_BYTES)             // 2 x 16384
#define SMEM_GEMM (SMG_W + 2 * W_CHUNK_BYTES) // 40960 B -> 2 CTAs/SM

#define PROJECT_BLOCKS ((NPTS + 255) / 256)   // 391
#define WCONV_BLOCKS   64

// ---------------- scratch (device globals: no allocation allowed) -------------
__device__ __align__(16) char g_Wbf16[C_PT * C_IMG * 2];    // bf16 W, chunked+swizzled
__device__ __align__(16) __half g_G[NPIX * C_PT];           // per-pixel aligned feat, 31.5 MB
__device__ float4 g_w[NPTS];
__device__ int4   g_off[NPTS];

// ---------------- helpers ------------------------------------------------------
__device__ __forceinline__ uint32_t smem_u32(const void* p) {
    uint32_t a;
    asm("{ .reg .u64 t; cvta.to.shared.u64 t, %1; cvt.u32.u64 %0, t; }"
        : "=r"(a) : "l"(p));
    return a;
}

#define LDSM_X4(r0, r1, r2, r3, addr) \
    asm volatile("ldmatrix.sync.aligned.m8n8.x4.shared.b16 {%0,%1,%2,%3}, [%4];" \
                 : "=r"(r0), "=r"(r1), "=r"(r2), "=r"(r3) : "r"(addr))

#define LDSM_X4_T(r0, r1, r2, r3, addr) \
    asm volatile("ldmatrix.sync.aligned.m8n8.x4.trans.shared.b16 {%0,%1,%2,%3}, [%4];" \
                 : "=r"(r0), "=r"(r1), "=r"(r2), "=r"(r3) : "r"(addr))

__device__ __forceinline__ void mma_bf16(float* d, const uint32_t* a,
                                         uint32_t b0, uint32_t b1) {
    asm volatile(
        "mma.sync.aligned.m16n8k16.row.col.f32.bf16.bf16.f32 "
        "{%0,%1,%2,%3}, {%4,%5,%6,%7}, {%8,%9}, {%0,%1,%2,%3};"
        : "+f"(d[0]), "+f"(d[1]), "+f"(d[2]), "+f"(d[3])
        : "r"(a[0]), "r"(a[1]), "r"(a[2]), "r"(a[3]), "r"(b0), "r"(b1));
}

#define CP_ASYNC16(dst, src) \
    asm volatile("cp.async.cg.shared.global [%0], [%1], 16;" \
                 :: "r"(dst), "l"(src) : "memory")
#define CP_COMMIT() asm volatile("cp.async.commit_group;" ::: "memory")
#define CP_WAIT_ALL() asm volatile("cp.async.wait_group 0;" ::: "memory")

// ================== kernel 1: project points + convert W (merged) =============
// blocks [0, PROJECT_BLOCKS): per-point projection (combined matrix per thread)
// blocks [PROJECT_BLOCKS, +WCONV_BLOCKS): align_w fp32 -> bf16 chunked+swizzled
__global__ void pre_kernel(const float* __restrict__ centers,
                           const int* __restrict__ bidx,
                           const float* __restrict__ P2,
                           const float* __restrict__ R0,
                           const float* __restrict__ Tr,
                           const float* __restrict__ aw) {
    const int t = threadIdx.x;
    if (blockIdx.x < PROJECT_BLOCKS) {
        int tid = blockIdx.x * 256 + t;
        if (tid >= NPTS) return;
        int b = bidx[tid];
        // combined M = P2[b] @ (R0[b] @ Tr[b])   (3x4)
        float A[16];
        #pragma unroll
        for (int i = 0; i < 4; ++i)
            #pragma unroll
            for (int j = 0; j < 4; ++j) {
                float s = 0.f;
                #pragma unroll
                for (int k = 0; k < 4; ++k)
                    s += R0[b*16 + i*4 + k] * Tr[b*16 + k*4 + j];
                A[i*4 + j] = s;
            }
        float M[12];
        #pragma unroll
        for (int i = 0; i < 3; ++i)
            #pragma unroll
            for (int j = 0; j < 4; ++j) {
                float s = 0.f;
                #pragma unroll
                for (int k = 0; k < 4; ++k)
                    s += P2[b*12 + i*4 + k] * A[k*4 + j];
                M[i*4 + j] = s;
            }
        float x = centers[tid * 3 + 0];
        float y = centers[tid * 3 + 1];
        float z = centers[tid * 3 + 2];
        float u  = M[0] * x + M[1] * y + M[2]  * z + M[3];
        float v  = M[4] * x + M[5] * y + M[6]  * z + M[7];
        float zc = M[8] * x + M[9] * y + M[10] * z + M[11];
        float depth = fmaxf(zc, 1e-5f);
        float uu = u / depth;
        float vv = v / depth;
        bool valid = (zc > 0.f) && (uu >= 0.f) && (uu < (float)IMW) &&
                     (vv >= 0.f) && (vv < (float)IMH);
        float x0f = floorf(uu), y0f = floorf(vv);
        float wx1 = uu - x0f, wx0 = 1.f - wx1;
        float wy1 = vv - y0f, wy0 = 1.f - wy1;
        int xi0 = (int)x0f, yi0 = (int)y0f;

        int   xs[4] = {xi0, xi0 + 1, xi0, xi0 + 1};
        int   ys[4] = {yi0, yi0, yi0 + 1, yi0 + 1};
        float ws[4] = {wx0 * wy0, wx1 * wy0, wx0 * wy1, wx1 * wy1};
        float wo[4];
        int   oo[4];
        #pragma unroll
        for (int j = 0; j < 4; ++j) {
            bool inb = (xs[j] >= 0) && (xs[j] <= IMW - 1) &&
                       (ys[j] >= 0) && (ys[j] <= IMH - 1);
            int xc = min(max(xs[j], 0), IMW - 1);
            int yc = min(max(ys[j], 0), IMH - 1);
            oo[j] = ((b * IMH + yc) * IMW + xc) * C_PT;   // offsets into G
            wo[j] = (valid && inb) ? ws[j] : 0.f;   // select, never multiply
        }
        g_w[tid]   = make_float4(wo[0], wo[1], wo[2], wo[3]);
        g_off[tid] = make_int4(oo[0], oo[1], oo[2], oo[3]);
    } else {
        // W: chunk c (16KB, K=32): n-row 64B = 4 16B-blocks,
        // block kb at byte c*16384 + n*64 + ((kb ^ ((n>>1)&3)) << 4)
        int idx = (blockIdx.x - PROJECT_BLOCKS) * 256 + t;
        int n   = idx >> 6;
        int kbg = idx & 63;
        int c   = kbg >> 2;
        int kb  = kbg & 3;
        const float4* src = (const float4*)&aw[(size_t)n * C_IMG + kbg * 8];
        float4 v0 = src[0];
        float4 v1 = src[1];
        uint32_t u[4];
        __nv_bfloat162 t0 = __float22bfloat162_rn(make_float2(v0.x, v0.y));
        __nv_bfloat162 t1 = __float22bfloat162_rn(make_float2(v0.z, v0.w));
        __nv_bfloat162 t2 = __float22bfloat162_rn(make_float2(v1.x, v1.y));
        __nv_bfloat162 t3 = __float22bfloat162_rn(make_float2(v1.z, v1.w));
        u[0] = *(uint32_t*)&t0; u[1] = *(uint32_t*)&t1;
        u[2] = *(uint32_t*)&t2; u[3] = *(uint32_t*)&t3;
        *(int4*)(g_Wbf16 + c * W_CHUNK_BYTES + n * 64 + ((kb ^ ((n >> 1) & 3)) << 4)) =
            *(int4*)u;
    }
}

// ================== kernel 2: dense pixel GEMM  G = img^T @ W^T ===============
// A = img in native (B,C,H,W) layout, staged fp32->bf16 per chunk, ldmatrix.trans.
// 512 threads = 16 warps, warp grid 2(Mpix) x 8(Nch). Warp tile 32x32.
__global__ void __launch_bounds__(512, 2)
gemm_kernel(const float* __restrict__ img) {
    extern __shared__ char sm[];
    uint32_t smb = smem_u32(sm);

    const int t    = threadIdx.x;
    const int lane = t & 31;
    const int warp = t >> 5;
    const int p0   = blockIdx.x * TM;          // global pixel base
    const int b    = p0 / PIXB;                // batch (tiles never cross)
    const int hw0  = p0 % PIXB;

    // A staging: thread owns (kloc = t>>4, px4 = (t&15)*4)
    const int kloc = t >> 4;
    const int px4  = (t & 15) * 4;
    const float* imgb = img + ((size_t)b * C_IMG) * PIXB + hw0 + px4;
    // STS address (swizzled): row kloc (128B), block px4>>3, offset (px4&7)*2
    const uint32_t asts = smb + SMG_A + kloc * 128 +
                          ((((unsigned)px4 >> 3) ^ (kloc & 7)) << 4) + (px4 & 4) * 2;

    // ---- prologue: stage img chunk 0, prefetch W chunk 0 -----------------------
    {
        float4 v = *(const float4*)(imgb + (size_t)kloc * PIXB);
        __nv_bfloat162 h0 = __float22bfloat162_rn(make_float2(v.x, v.y));
        __nv_bfloat162 h1 = __float22bfloat162_rn(make_float2(v.z, v.w));
        asm volatile("st.shared.v2.b32 [%0], {%1, %2};"
                     :: "r"(asts), "r"(*(uint32_t*)&h0), "r"(*(uint32_t*)&h1));
    }
    {
        const char* src = g_Wbf16;
        uint32_t dst = smb + SMG_W;
        CP_ASYNC16(dst + t * 16, src + (size_t)t * 16);
        CP_ASYNC16(dst + (t + 512) * 16, src + (size_t)(t + 512) * 16);
        CP_COMMIT();
    }

    const int wm = warp & 1;    // pixel group (32 rows)
    const int wn = warp >> 1;   // channel group (32 cols)
    float acc[2][4][4];
    #pragma unroll
    for (int i = 0; i < 2; ++i)
        #pragma unroll
        for (int j = 0; j < 4; ++j)
            #pragma unroll
            for (int r = 0; r < 4; ++r) acc[i][j][r] = 0.f;

    // A (trans) lane addressing: krow = (lane&7) | ((lane>>4)<<3), mhalf = (lane>>3)&1
    const int krow  = (lane & 7) | ((lane >> 4) << 3);
    const int mhalf = (lane >> 3) & 1;
    // per-i swizzled block: ((pm>>3) + mhalf) ^ (lane&7), pm = wm*32 + i*16
    const uint32_t ablk0 = ((unsigned)((wm * 32) >> 3) + mhalf) ^ (lane & 7);
    const uint32_t ablk1 = ((unsigned)((wm * 32 + 16) >> 3) + mhalf) ^ (lane & 7);
    const uint32_t abase0 = krow * 128 + (ablk0 << 4);
    const uint32_t abase1 = krow * 128 + (ablk1 << 4);
    // B (W) lane addressing (as round 7)
    const int brow  = wn * 32 + (lane >> 4) * 8 + (lane & 7);
    const int bhalf = (lane >> 3) & 1;

    CP_WAIT_ALL();
    __syncthreads();

    for (int c = 0; c < NCHUNK; ++c) {
        float4 v;
        if (c + 1 < NCHUNK) {
            // prefetch img chunk c+1 (LDG; consumed after MMA below)
            v = *(const float4*)(imgb + (size_t)((c + 1) * 32 + kloc) * PIXB);
            // prefetch W chunk c+1
            const char* src = g_Wbf16 + (size_t)(c + 1) * W_CHUNK_BYTES;
            uint32_t dst = smb + SMG_W + ((c + 1) & 1) * W_CHUNK_BYTES;
            CP_ASYNC16(dst + t * 16, src + (size_t)t * 16);
            CP_ASYNC16(dst + (t + 512) * 16, src + (size_t)(t + 512) * 16);
            CP_COMMIT();
        }
        const uint32_t abuf = smb + SMG_A + (c & 1) * A_CHUNK_BYTES;
        const uint32_t wbuf = smb + SMG_W + (c & 1) * W_CHUNK_BYTES;

        #pragma unroll
        for (int ks = 0; ks < 2; ++ks) {
            uint32_t a[2][4];
            LDSM_X4_T(a[0][0], a[0][1], a[0][2], a[0][3],
                      abuf + ks * 2048 + abase0);
            LDSM_X4_T(a[1][0], a[1][1], a[1][2], a[1][3],
                      abuf + ks * 2048 + abase1);
            #pragma unroll
            for (int jj = 0; jj < 2; ++jj) {
                uint32_t b0, b1, b2, b3;
                int nrow = brow + jj * 16;
                int kb   = (ks * 2 + bhalf) ^ ((nrow >> 1) & 3);
                LDSM_X4(b0, b1, b2, b3, wbuf + nrow * 64 + (kb << 4));
                mma_bf16(acc[0][2 * jj],     a[0], b0, b1);
                mma_bf16(acc[0][2 * jj + 1], a[0], b2, b3);
                mma_bf16(acc[1][2 * jj],     a[1], b0, b1);
                mma_bf16(acc[1][2 * jj + 1], a[1], b2, b3);
            }
        }

        if (c + 1 < NCHUNK) {
            // convert + store img chunk c+1 into the other A buffer
            __nv_bfloat162 h0 = __float22bfloat162_rn(make_float2(v.x, v.y));
            __nv_bfloat162 h1 = __float22bfloat162_rn(make_float2(v.z, v.w));
            uint32_t dst = asts + (((c + 1) & 1) ? A_CHUNK_BYTES : 0);
            asm volatile("st.shared.v2.b32 [%0], {%1, %2};"
                         :: "r"(dst), "r"(*(uint32_t*)&h0), "r"(*(uint32_t*)&h1));
        }
        CP_WAIT_ALL();
        __syncthreads();
    }

    // ---- epilogue: G[pixel][col] = acc (fp16) -----------------------------------
    const int cbase = wn * 32 + (lane & 3) * 2;
    const int rbase = p0 + wm * 32 + (lane >> 2);
    #pragma unroll
    for (int i = 0; i < 2; ++i) {
        #pragma unroll
        for (int half = 0; half < 2; ++half) {
            int pix = rbase + i * 16 + half * 8;
            #pragma unroll
            for (int j = 0; j < 4; ++j) {
                int col = cbase + j * 8;
                __half2 h = __floats2half2_rn(acc[i][j][half * 2 + 0],
                                              acc[i][j][half * 2 + 1]);
                *(__half2*)&g_G[(size_t)pix * C_PT + col] = h;
            }
        }
    }
}

// ================== kernel 3: per-point blend + residual ======================
// 1 warp per point; lane owns 8 channels. G is L2-resident (31.5 MB).
__global__ void __launch_bounds__(256)
blend_kernel(const float* __restrict__ point_feat,
             const float* __restrict__ align_b,
             float* __restrict__ out) {
    const int lane = threadIdx.x & 31;
    const int p    = blockIdx.x * 8 + (threadIdx.x >> 5);
    const int ch   = lane * 8;

    float4 w = g_w[p];
    int4   o = g_off[p];
    uint4 c0 = *(const uint4*)(g_G + o.x + ch);
    uint4 c1 = *(const uint4*)(g_G + o.y + ch);
    uint4 c2 = *(const uint4*)(g_G + o.z + ch);
    uint4 c3 = *(const uint4*)(g_G + o.w + ch);

    float acc[8];
    #pragma unroll
    for (int k = 0; k < 4; ++k) {
        float2 f0 = __half22float2(((const __half2*)&c0)[k]);
        float2 f1 = __half22float2(((const __half2*)&c1)[k]);
        float2 f2 = __half22float2(((const __half2*)&c2)[k]);
        float2 f3 = __half22float2(((const __half2*)&c3)[k]);
        acc[2*k+0] = w.x * f0.x + w.y * f1.x + w.z * f2.x + w.w * f3.x;
        acc[2*k+1] = w.x * f0.y + w.y * f1.y + w.z * f2.y + w.w * f3.y;
    }

    const float4* pf = (const float4*)&point_feat[(size_t)p * C_PT + ch];
    const float4* bb = (const float4*)&align_b[ch];
    float4* op = (float4*)&out[(size_t)p * C_PT + ch];
    #pragma unroll
    for (int k = 0; k < 2; ++k) {
        float4 a = pf[k];
        float4 bv = bb[k];
        float4 r;
        r.x = a.x + bv.x + acc[4*k+0];
        r.y = a.y + bv.y + acc[4*k+1];
        r.z = a.z + bv.z + acc[4*k+2];
        r.w = a.w + bv.w + acc[4*k+3];
        op[k] = r;
    }
}

// ================== launcher ==================================================
extern "C" void kernel_launch(void* const* d_in, const int* in_sizes, int n_in,
                              void* d_out, int out_size) {
    const float* point_feat = (const float*)d_in[0];
    const float* centers    = (const float*)d_in[1];
    const float* img        = (const float*)d_in[2];
    const float* P2         = (const float*)d_in[3];
    const float* R0         = (const float*)d_in[4];
    const float* Tr         = (const float*)d_in[5];
    const float* align_w    = (const float*)d_in[6];
    const float* align_b    = (const float*)d_in[7];
    const int*   bidx       = (const int*)d_in[8];
    float* out = (float*)d_out;

    pre_kernel<<<PROJECT_BLOCKS + WCONV_BLOCKS, 256>>>(centers, bidx, P2, R0, Tr,
                                                       align_w);
    cudaFuncSetAttribute(gemm_kernel,
                         cudaFuncAttributeMaxDynamicSharedMemorySize, SMEM_GEMM);
    gemm_kernel<<<NPIX / TM, 512, SMEM_GEMM>>>(img);
    blend_kernel<<<NPTS / 8, 256>>>(point_feat, align_b, out);
}

// round 9
// speedup vs baseline: 1.9577x; 1.0847x over previous
#include <cuda_runtime.h>
#include <cuda_fp16.h>
#include <cuda_bf16.h>
#include <cstdint>

// Problem constants (fixed by the reference)
#define NPTS   100000
#define C_IMG  512
#define C_PT   256
#define BSZ    8
#define IMH    48
#define IMW    160
#define NPIX   (BSZ * IMH * IMW)     // 61440
#define PIXB   (IMH * IMW)           // 7680 pixels per batch

#define TM     64                // pixels per CTA (GEMM M tile)
#define NCHUNK 16                // K chunks of 32
#define W_CHUNK_BYTES 16384      // 256 n-rows x 32 k x 2B (swizzled, 64B rows)
#define A_CHUNK_BYTES 4096       // 32 k-rows x 64 pix x 2B (swizzled, 128B rows)

// GEMM smem layout
#define SMG_A 0                               // 2 x 4096
#define SMG_W (2 * A_CHUNK_BYTES)             // 2 x 16384
#define SMEM_GEMM (SMG_W + 2 * W_CHUNK_BYTES) // 40960 B -> 2 CTAs/SM

#define PROJECT_BLOCKS ((NPTS + 255) / 256)   // 391
#define WCONV_BLOCKS   64

// ---------------- scratch (device globals: no allocation allowed) -------------
__device__ __align__(16) char g_Wbf16[C_PT * C_IMG * 2];    // bf16 W, chunked+swizzled
__device__ __align__(16) __half g_G[NPIX * C_PT];           // per-pixel aligned feat, 31.5 MB
__device__ float4 g_w[NPTS];
__device__ int4   g_off[NPTS];

// ---------------- helpers ------------------------------------------------------
__device__ __forceinline__ uint32_t smem_u32(const void* p) {
    uint32_t a;
    asm("{ .reg .u64 t; cvta.to.shared.u64 t, %1; cvt.u32.u64 %0, t; }"
        : "=r"(a) : "l"(p));
    return a;
}

#define LDSM_X4(r0, r1, r2, r3, addr) \
    asm volatile("ldmatrix.sync.aligned.m8n8.x4.shared.b16 {%0,%1,%2,%3}, [%4];" \
                 : "=r"(r0), "=r"(r1), "=r"(r2), "=r"(r3) : "r"(addr))

#define LDSM_X4_T(r0, r1, r2, r3, addr) \
    asm volatile("ldmatrix.sync.aligned.m8n8.x4.trans.shared.b16 {%0,%1,%2,%3}, [%4];" \
                 : "=r"(r0), "=r"(r1), "=r"(r2), "=r"(r3) : "r"(addr))

__device__ __forceinline__ void mma_bf16(float* d, const uint32_t* a,
                                         uint32_t b0, uint32_t b1) {
    asm volatile(
        "mma.sync.aligned.m16n8k16.row.col.f32.bf16.bf16.f32 "
        "{%0,%1,%2,%3}, {%4,%5,%6,%7}, {%8,%9}, {%0,%1,%2,%3};"
        : "+f"(d[0]), "+f"(d[1]), "+f"(d[2]), "+f"(d[3])
        : "r"(a[0]), "r"(a[1]), "r"(a[2]), "r"(a[3]), "r"(b0), "r"(b1));
}

#define CP_ASYNC16(dst, src) \
    asm volatile("cp.async.cg.shared.global [%0], [%1], 16;" \
                 :: "r"(dst), "l"(src) : "memory")
#define CP_COMMIT() asm volatile("cp.async.commit_group;" ::: "memory")
#define CP_WAIT_ALL() asm volatile("cp.async.wait_group 0;" ::: "memory")

// ================== kernel 1: project points + convert W (merged) =============
__global__ void pre_kernel(const float* __restrict__ centers,
                           const int* __restrict__ bidx,
                           const float* __restrict__ P2,
                           const float* __restrict__ R0,
                           const float* __restrict__ Tr,
                           const float* __restrict__ aw) {
    const int t = threadIdx.x;
    if (blockIdx.x < PROJECT_BLOCKS) {
        int tid = blockIdx.x * 256 + t;
        if (tid >= NPTS) return;
        int b = bidx[tid];
        // combined M = P2[b] @ (R0[b] @ Tr[b])   (3x4)
        float A[16];
        #pragma unroll
        for (int i = 0; i < 4; ++i)
            #pragma unroll
            for (int j = 0; j < 4; ++j) {
                float s = 0.f;
                #pragma unroll
                for (int k = 0; k < 4; ++k)
                    s += R0[b*16 + i*4 + k] * Tr[b*16 + k*4 + j];
                A[i*4 + j] = s;
            }
        float M[12];
        #pragma unroll
        for (int i = 0; i < 3; ++i)
            #pragma unroll
            for (int j = 0; j < 4; ++j) {
                float s = 0.f;
                #pragma unroll
                for (int k = 0; k < 4; ++k)
                    s += P2[b*12 + i*4 + k] * A[k*4 + j];
                M[i*4 + j] = s;
            }
        float x = centers[tid * 3 + 0];
        float y = centers[tid * 3 + 1];
        float z = centers[tid * 3 + 2];
        float u  = M[0] * x + M[1] * y + M[2]  * z + M[3];
        float v  = M[4] * x + M[5] * y + M[6]  * z + M[7];
        float zc = M[8] * x + M[9] * y + M[10] * z + M[11];
        float depth = fmaxf(zc, 1e-5f);
        float uu = u / depth;
        float vv = v / depth;
        bool valid = (zc > 0.f) && (uu >= 0.f) && (uu < (float)IMW) &&
                     (vv >= 0.f) && (vv < (float)IMH);
        float x0f = floorf(uu), y0f = floorf(vv);
        float wx1 = uu - x0f, wx0 = 1.f - wx1;
        float wy1 = vv - y0f, wy0 = 1.f - wy1;
        int xi0 = (int)x0f, yi0 = (int)y0f;

        int   xs[4] = {xi0, xi0 + 1, xi0, xi0 + 1};
        int   ys[4] = {yi0, yi0, yi0 + 1, yi0 + 1};
        float ws[4] = {wx0 * wy0, wx1 * wy0, wx0 * wy1, wx1 * wy1};
        float wo[4];
        int   oo[4];
        #pragma unroll
        for (int j = 0; j < 4; ++j) {
            bool inb = (xs[j] >= 0) && (xs[j] <= IMW - 1) &&
                       (ys[j] >= 0) && (ys[j] <= IMH - 1);
            int xc = min(max(xs[j], 0), IMW - 1);
            int yc = min(max(ys[j], 0), IMH - 1);
            oo[j] = ((b * IMH + yc) * IMW + xc) * C_PT;   // offsets into G
            wo[j] = (valid && inb) ? ws[j] : 0.f;   // select, never multiply
        }
        g_w[tid]   = make_float4(wo[0], wo[1], wo[2], wo[3]);
        g_off[tid] = make_int4(oo[0], oo[1], oo[2], oo[3]);
    } else {
        // W: chunk c (16KB, K=32): n-row 64B = 4 16B-blocks,
        // block kb at byte c*16384 + n*64 + ((kb ^ ((n>>1)&3)) << 4)
        int idx = (blockIdx.x - PROJECT_BLOCKS) * 256 + t;
        int n   = idx >> 6;
        int kbg = idx & 63;
        int c   = kbg >> 2;
        int kb  = kbg & 3;
        const float4* src = (const float4*)&aw[(size_t)n * C_IMG + kbg * 8];
        float4 v0 = src[0];
        float4 v1 = src[1];
        uint32_t u[4];
        __nv_bfloat162 t0 = __float22bfloat162_rn(make_float2(v0.x, v0.y));
        __nv_bfloat162 t1 = __float22bfloat162_rn(make_float2(v0.z, v0.w));
        __nv_bfloat162 t2 = __float22bfloat162_rn(make_float2(v1.x, v1.y));
        __nv_bfloat162 t3 = __float22bfloat162_rn(make_float2(v1.z, v1.w));
        u[0] = *(uint32_t*)&t0; u[1] = *(uint32_t*)&t1;
        u[2] = *(uint32_t*)&t2; u[3] = *(uint32_t*)&t3;
        *(int4*)(g_Wbf16 + c * W_CHUNK_BYTES + n * 64 + ((kb ^ ((n >> 1) & 3)) << 4)) =
            *(int4*)u;
    }
}

// ================== kernel 2: dense pixel GEMM  G = img^T @ W^T ===============
// A = img in native (B,C,H,W) layout, staged fp32->bf16 per chunk, ldmatrix.trans.
// 256 threads = 8 warps, warp grid 2(Mpix) x 4(Nch). Warp tile 32x64.
__global__ void __launch_bounds__(256, 2)
gemm_kernel(const float* __restrict__ img) {
    extern __shared__ char sm[];
    uint32_t smb = smem_u32(sm);

    const int t    = threadIdx.x;
    const int lane = t & 31;
    const int warp = t >> 5;
    const int p0   = blockIdx.x * TM;          // global pixel base
    const int b    = p0 / PIXB;                // batch (tiles never cross)
    const int hw0  = p0 % PIXB;

    // A staging: thread owns k-row kloc (0..31), pixel block px8 (8 px = 16B bf16)
    const int kloc = t >> 3;
    const int px8  = (t & 7) * 8;
    const float* imgb = img + ((size_t)b * C_IMG) * PIXB + hw0 + px8;
    const uint32_t asts = smb + SMG_A + kloc * 128 +
                          ((((unsigned)px8 >> 3) ^ (kloc & 7)) << 4);

    // ---- prologue: stage img chunk 0, prefetch W chunk 0 -----------------------
    {
        float4 v0 = *(const float4*)(imgb + (size_t)kloc * PIXB);
        float4 v1 = *(const float4*)(imgb + (size_t)kloc * PIXB + 4);
        __nv_bfloat162 h0 = __float22bfloat162_rn(make_float2(v0.x, v0.y));
        __nv_bfloat162 h1 = __float22bfloat162_rn(make_float2(v0.z, v0.w));
        __nv_bfloat162 h2 = __float22bfloat162_rn(make_float2(v1.x, v1.y));
        __nv_bfloat162 h3 = __float22bfloat162_rn(make_float2(v1.z, v1.w));
        asm volatile("st.shared.v4.b32 [%0], {%1, %2, %3, %4};"
                     :: "r"(asts), "r"(*(uint32_t*)&h0), "r"(*(uint32_t*)&h1),
                        "r"(*(uint32_t*)&h2), "r"(*(uint32_t*)&h3));
    }
    {
        const char* src = g_Wbf16;
        uint32_t dst = smb + SMG_W;
        #pragma unroll
        for (int j = 0; j < 4; ++j)
            CP_ASYNC16(dst + (t + j * 256) * 16, src + (size_t)(t + j * 256) * 16);
        CP_COMMIT();
    }

    const int wm = warp & 1;    // pixel group (32 rows)
    const int wn = warp >> 1;   // channel group (64 cols)
    float acc[2][8][4];
    #pragma unroll
    for (int i = 0; i < 2; ++i)
        #pragma unroll
        for (int j = 0; j < 8; ++j)
            #pragma unroll
            for (int r = 0; r < 4; ++r) acc[i][j][r] = 0.f;

    // A (trans) lane addressing
    const int krow  = (lane & 7) | ((lane >> 4) << 3);
    const int mhalf = (lane >> 3) & 1;
    const uint32_t ablk0 = ((unsigned)((wm * 32) >> 3) + mhalf) ^ (lane & 7);
    const uint32_t ablk1 = ((unsigned)((wm * 32 + 16) >> 3) + mhalf) ^ (lane & 7);
    const uint32_t abase0 = krow * 128 + (ablk0 << 4);
    const uint32_t abase1 = krow * 128 + (ablk1 << 4);
    // B (W) lane addressing
    const int brow  = wn * 64 + (lane >> 4) * 8 + (lane & 7);
    const int bhalf = (lane >> 3) & 1;

    CP_WAIT_ALL();
    __syncthreads();

    for (int c = 0; c < NCHUNK; ++c) {
        float4 v0, v1;
        if (c + 1 < NCHUNK) {
            // prefetch img chunk c+1 (LDG; consumed after MMA below)
            const float* s = imgb + (size_t)((c + 1) * 32 + kloc) * PIXB;
            v0 = *(const float4*)(s);
            v1 = *(const float4*)(s + 4);
            // prefetch W chunk c+1
            const char* src = g_Wbf16 + (size_t)(c + 1) * W_CHUNK_BYTES;
            uint32_t dst = smb + SMG_W + ((c + 1) & 1) * W_CHUNK_BYTES;
            #pragma unroll
            for (int j = 0; j < 4; ++j)
                CP_ASYNC16(dst + (t + j * 256) * 16, src + (size_t)(t + j * 256) * 16);
            CP_COMMIT();
        }
        const uint32_t abuf = smb + SMG_A + (c & 1) * A_CHUNK_BYTES;
        const uint32_t wbuf = smb + SMG_W + (c & 1) * W_CHUNK_BYTES;

        #pragma unroll
        for (int ks = 0; ks < 2; ++ks) {
            uint32_t a[2][4];
            LDSM_X4_T(a[0][0], a[0][1], a[0][2], a[0][3],
                      abuf + ks * 2048 + abase0);
            LDSM_X4_T(a[1][0], a[1][1], a[1][2], a[1][3],
                      abuf + ks * 2048 + abase1);
            #pragma unroll
            for (int jj = 0; jj < 4; ++jj) {
                uint32_t b0, b1, b2, b3;
                int nrow = brow + jj * 16;
                int kb   = (ks * 2 + bhalf) ^ ((nrow >> 1) & 3);
                LDSM_X4(b0, b1, b2, b3, wbuf + nrow * 64 + (kb << 4));
                mma_bf16(acc[0][2 * jj],     a[0], b0, b1);
                mma_bf16(acc[0][2 * jj + 1], a[0], b2, b3);
                mma_bf16(acc[1][2 * jj],     a[1], b0, b1);
                mma_bf16(acc[1][2 * jj + 1], a[1], b2, b3);
            }
        }

        if (c + 1 < NCHUNK) {
            // convert + store img chunk c+1 into the other A buffer
            __nv_bfloat162 h0 = __float22bfloat162_rn(make_float2(v0.x, v0.y));
            __nv_bfloat162 h1 = __float22bfloat162_rn(make_float2(v0.z, v0.w));
            __nv_bfloat162 h2 = __float22bfloat162_rn(make_float2(v1.x, v1.y));
            __nv_bfloat162 h3 = __float22bfloat162_rn(make_float2(v1.z, v1.w));
            uint32_t dst = asts + (((c + 1) & 1) ? A_CHUNK_BYTES : 0);
            asm volatile("st.shared.v4.b32 [%0], {%1, %2, %3, %4};"
                         :: "r"(dst), "r"(*(uint32_t*)&h0), "r"(*(uint32_t*)&h1),
                            "r"(*(uint32_t*)&h2), "r"(*(uint32_t*)&h3));
        }
        CP_WAIT_ALL();
        __syncthreads();
    }

    // ---- epilogue: G[pixel][col] = acc (fp16) -----------------------------------
    const int cbase = wn * 64 + (lane & 3) * 2;
    const int rbase = p0 + wm * 32 + (lane >> 2);
    #pragma unroll
    for (int i = 0; i < 2; ++i) {
        #pragma unroll
        for (int half = 0; half < 2; ++half) {
            int pix = rbase + i * 16 + half * 8;
            #pragma unroll
            for (int j = 0; j < 8; ++j) {
                int col = cbase + j * 8;
                __half2 h = __floats2half2_rn(acc[i][j][half * 2 + 0],
                                              acc[i][j][half * 2 + 1]);
                *(__half2*)&g_G[(size_t)pix * C_PT + col] = h;
            }
        }
    }
}

// ================== kernel 3: per-point blend + residual ======================
// 1 warp per point; lane owns 8 channels. G is L2-resident (31.5 MB).
__global__ void __launch_bounds__(256)
blend_kernel(const float* __restrict__ point_feat,
             const float* __restrict__ align_b,
             float* __restrict__ out) {
    const int lane = threadIdx.x & 31;
    const int p    = blockIdx.x * 8 + (threadIdx.x >> 5);
    const int ch   = lane * 8;

    float4 w = g_w[p];
    int4   o = g_off[p];
    uint4 c0 = *(const uint4*)(g_G + o.x + ch);
    uint4 c1 = *(const uint4*)(g_G + o.y + ch);
    uint4 c2 = *(const uint4*)(g_G + o.z + ch);
    uint4 c3 = *(const uint4*)(g_G + o.w + ch);

    float acc[8];
    #pragma unroll
    for (int k = 0; k < 4; ++k) {
        float2 f0 = __half22float2(((const __half2*)&c0)[k]);
        float2 f1 = __half22float2(((const __half2*)&c1)[k]);
        float2 f2 = __half22float2(((const __half2*)&c2)[k]);
        float2 f3 = __half22float2(((const __half2*)&c3)[k]);
        acc[2*k+0] = w.x * f0.x + w.y * f1.x + w.z * f2.x + w.w * f3.x;
        acc[2*k+1] = w.x * f0.y + w.y * f1.y + w.z * f2.y + w.w * f3.y;
    }

    const float4* pf = (const float4*)&point_feat[(size_t)p * C_PT + ch];
    const float4* bb = (const float4*)&align_b[ch];
    float4* op = (float4*)&out[(size_t)p * C_PT + ch];
    #pragma unroll
    for (int k = 0; k < 2; ++k) {
        float4 a = pf[k];
        float4 bv = bb[k];
        float4 r;
        r.x = a.x + bv.x + acc[4*k+0];
        r.y = a.y + bv.y + acc[4*k+1];
        r.z = a.z + bv.z + acc[4*k+2];
        r.w = a.w + bv.w + acc[4*k+3];
        op[k] = r;
    }
}

// ================== launcher ==================================================
extern "C" void kernel_launch(void* const* d_in, const int* in_sizes, int n_in,
                              void* d_out, int out_size) {
    const float* point_feat = (const float*)d_in[0];
    const float* centers    = (const float*)d_in[1];
    const float* img        = (const float*)d_in[2];
    const float* P2         = (const float*)d_in[3];
    const float* R0         = (const float*)d_in[4];
    const float* Tr         = (const float*)d_in[5];
    const float* align_w    = (const float*)d_in[6];
    const float* align_b    = (const float*)d_in[7];
    const int*   bidx       = (const int*)d_in[8];
    float* out = (float*)d_out;

    pre_kernel<<<PROJECT_BLOCKS + WCONV_BLOCKS, 256>>>(centers, bidx, P2, R0, Tr,
                                                       align_w);
    cudaFuncSetAttribute(gemm_kernel,
                         cudaFuncAttributeMaxDynamicSharedMemorySize, SMEM_GEMM);
    gemm_kernel<<<NPIX / TM, 256, SMEM_GEMM>>>(img);
    blend_kernel<<<NPTS / 8, 256>>>(point_feat, align_b, out);
}

// round 10
// speedup vs baseline: 2.5968x; 1.3265x over previous
#include <cuda_runtime.h>
#include <cuda_fp16.h>
#include <cuda_bf16.h>
#include <cstdint>

// Problem constants (fixed by the reference)
#define NPTS   100000
#define C_IMG  512
#define C_PT   256
#define BSZ    8
#define IMH    48
#define IMW    160
#define NPIX   (BSZ * IMH * IMW)     // 61440
#define PIXB   (IMH * IMW)           // 7680 pixels per batch

#define TM     64                // pixels per CTA (GEMM M tile)
#define NTILE  (NPIX / TM)       // 960 G tiles
#define NCHUNK 16                // K chunks of 32
#define W_CHUNK_BYTES 16384      // 256 n-rows x 32 k x 2B (swizzled, 64B rows)
#define A_CHUNK_BYTES 4096       // 32 k-rows x 64 pix x 2B (swizzled, 128B rows)

// GEMM smem layout
#define SMG_A 0                               // 2 x 4096
#define SMG_W (2 * A_CHUNK_BYTES)             // 2 x 16384
#define SMEM_GEMM (SMG_W + 2 * W_CHUNK_BYTES) // 40960 B -> 2 CTAs/SM

#define PROJECT_BLOCKS ((NPTS + 255) / 256)   // 391
#define WCONV_BLOCKS   64

// ---------------- scratch (device globals: no allocation allowed) -------------
__device__ __align__(16) char g_Wbf16[C_PT * C_IMG * 2];    // bf16 W, chunked+swizzled
__device__ __align__(16) __half g_G[NPIX * C_PT];           // per-pixel aligned feat, 31.5 MB
__device__ float4 g_w[NPTS];
__device__ int4   g_off[NPTS];
__device__ int    g_tileflag[NTILE];          // 1 = tile referenced by some point

// ---------------- helpers ------------------------------------------------------
__device__ __forceinline__ uint32_t smem_u32(const void* p) {
    uint32_t a;
    asm("{ .reg .u64 t; cvta.to.shared.u64 t, %1; cvt.u32.u64 %0, t; }"
        : "=r"(a) : "l"(p));
    return a;
}

#define LDSM_X4(r0, r1, r2, r3, addr) \
    asm volatile("ldmatrix.sync.aligned.m8n8.x4.shared.b16 {%0,%1,%2,%3}, [%4];" \
                 : "=r"(r0), "=r"(r1), "=r"(r2), "=r"(r3) : "r"(addr))

#define LDSM_X4_T(r0, r1, r2, r3, addr) \
    asm volatile("ldmatrix.sync.aligned.m8n8.x4.trans.shared.b16 {%0,%1,%2,%3}, [%4];" \
                 : "=r"(r0), "=r"(r1), "=r"(r2), "=r"(r3) : "r"(addr))

__device__ __forceinline__ void mma_bf16(float* d, const uint32_t* a,
                                         uint32_t b0, uint32_t b1) {
    asm volatile(
        "mma.sync.aligned.m16n8k16.row.col.f32.bf16.bf16.f32 "
        "{%0,%1,%2,%3}, {%4,%5,%6,%7}, {%8,%9}, {%0,%1,%2,%3};"
        : "+f"(d[0]), "+f"(d[1]), "+f"(d[2]), "+f"(d[3])
        : "r"(a[0]), "r"(a[1]), "r"(a[2]), "r"(a[3]), "r"(b0), "r"(b1));
}

#define CP_ASYNC16(dst, src) \
    asm volatile("cp.async.cg.shared.global [%0], [%1], 16;" \
                 :: "r"(dst), "l"(src) : "memory")
#define CP_COMMIT() asm volatile("cp.async.commit_group;" ::: "memory")
#define CP_WAIT_ALL() asm volatile("cp.async.wait_group 0;" ::: "memory")

// ================== kernel 1: project points + convert W (merged) =============
__global__ void pre_kernel(const float* __restrict__ centers,
                           const int* __restrict__ bidx,
                           const float* __restrict__ P2,
                           const float* __restrict__ R0,
                           const float* __restrict__ Tr,
                           const float* __restrict__ aw) {
    const int t = threadIdx.x;
    if (blockIdx.x < PROJECT_BLOCKS) {
        int tid = blockIdx.x * 256 + t;
        if (tid >= NPTS) return;
        int b = bidx[tid];
        // combined M = P2[b] @ (R0[b] @ Tr[b])   (3x4)
        float A[16];
        #pragma unroll
        for (int i = 0; i < 4; ++i)
            #pragma unroll
            for (int j = 0; j < 4; ++j) {
                float s = 0.f;
                #pragma unroll
                for (int k = 0; k < 4; ++k)
                    s += R0[b*16 + i*4 + k] * Tr[b*16 + k*4 + j];
                A[i*4 + j] = s;
            }
        float M[12];
        #pragma unroll
        for (int i = 0; i < 3; ++i)
            #pragma unroll
            for (int j = 0; j < 4; ++j) {
                float s = 0.f;
                #pragma unroll
                for (int k = 0; k < 4; ++k)
                    s += P2[b*12 + i*4 + k] * A[k*4 + j];
                M[i*4 + j] = s;
            }
        float x = centers[tid * 3 + 0];
        float y = centers[tid * 3 + 1];
        float z = centers[tid * 3 + 2];
        float u  = M[0] * x + M[1] * y + M[2]  * z + M[3];
        float v  = M[4] * x + M[5] * y + M[6]  * z + M[7];
        float zc = M[8] * x + M[9] * y + M[10] * z + M[11];
        float depth = fmaxf(zc, 1e-5f);
        float uu = u / depth;
        float vv = v / depth;
        bool valid = (zc > 0.f) && (uu >= 0.f) && (uu < (float)IMW) &&
                     (vv >= 0.f) && (vv < (float)IMH);
        float x0f = floorf(uu), y0f = floorf(vv);
        float wx1 = uu - x0f, wx0 = 1.f - wx1;
        float wy1 = vv - y0f, wy0 = 1.f - wy1;
        int xi0 = (int)x0f, yi0 = (int)y0f;

        int   xs[4] = {xi0, xi0 + 1, xi0, xi0 + 1};
        int   ys[4] = {yi0, yi0, yi0 + 1, yi0 + 1};
        float ws[4] = {wx0 * wy0, wx1 * wy0, wx0 * wy1, wx1 * wy1};
        float wo[4];
        int   oo[4];
        #pragma unroll
        for (int j = 0; j < 4; ++j) {
            bool inb = (xs[j] >= 0) && (xs[j] <= IMW - 1) &&
                       (ys[j] >= 0) && (ys[j] <= IMH - 1);
            int xc = min(max(xs[j], 0), IMW - 1);
            int yc = min(max(ys[j], 0), IMH - 1);
            oo[j] = ((b * IMH + yc) * IMW + xc) * C_PT;   // offsets into G
            wo[j] = (valid && inb) ? ws[j] : 0.f;   // select, never multiply
        }
        g_w[tid]   = make_float4(wo[0], wo[1], wo[2], wo[3]);
        g_off[tid] = make_int4(oo[0], oo[1], oo[2], oo[3]);
        // mark referenced G tiles (idempotent plain stores; offsets are read
        // by blend_kernel regardless of weight, so flag all four)
        g_tileflag[oo[0] >> 14] = 1;
        g_tileflag[oo[1] >> 14] = 1;
        g_tileflag[oo[2] >> 14] = 1;
        g_tileflag[oo[3] >> 14] = 1;
    } else {
        // W: chunk c (16KB, K=32): n-row 64B = 4 16B-blocks,
        // block kb at byte c*16384 + n*64 + ((kb ^ ((n>>1)&3)) << 4)
        int idx = (blockIdx.x - PROJECT_BLOCKS) * 256 + t;
        int n   = idx >> 6;
        int kbg = idx & 63;
        int c   = kbg >> 2;
        int kb  = kbg & 3;
        const float4* src = (const float4*)&aw[(size_t)n * C_IMG + kbg * 8];
        float4 v0 = src[0];
        float4 v1 = src[1];
        uint32_t u[4];
        __nv_bfloat162 t0 = __float22bfloat162_rn(make_float2(v0.x, v0.y));
        __nv_bfloat162 t1 = __float22bfloat162_rn(make_float2(v0.z, v0.w));
        __nv_bfloat162 t2 = __float22bfloat162_rn(make_float2(v1.x, v1.y));
        __nv_bfloat162 t3 = __float22bfloat162_rn(make_float2(v1.z, v1.w));
        u[0] = *(uint32_t*)&t0; u[1] = *(uint32_t*)&t1;
        u[2] = *(uint32_t*)&t2; u[3] = *(uint32_t*)&t3;
        *(int4*)(g_Wbf16 + c * W_CHUNK_BYTES + n * 64 + ((kb ^ ((n >> 1) & 3)) << 4)) =
            *(int4*)u;
    }
}

// ================== kernel 2: dense pixel GEMM  G = img^T @ W^T ===============
// A = img in native (B,C,H,W) layout, staged fp32->bf16 per chunk, ldmatrix.trans.
// 256 threads = 8 warps, warp grid 2(Mpix) x 4(Nch). Warp tile 32x64.
// CTAs whose 64-pixel tile is never referenced by any point exit immediately.
__global__ void __launch_bounds__(256, 2)
gemm_kernel(const float* __restrict__ img) {
    if (g_tileflag[blockIdx.x] == 0) return;   // uniform early exit

    extern __shared__ char sm[];
    uint32_t smb = smem_u32(sm);

    const int t    = threadIdx.x;
    const int lane = t & 31;
    const int warp = t >> 5;
    const int p0   = blockIdx.x * TM;          // global pixel base
    const int b    = p0 / PIXB;                // batch (tiles never cross)
    const int hw0  = p0 % PIXB;

    // A staging: thread owns k-row kloc (0..31), pixel block px8 (8 px = 16B bf16)
    const int kloc = t >> 3;
    const int px8  = (t & 7) * 8;
    const float* imgb = img + ((size_t)b * C_IMG) * PIXB + hw0 + px8;
    const uint32_t asts = smb + SMG_A + kloc * 128 +
                          ((((unsigned)px8 >> 3) ^ (kloc & 7)) << 4);

    // ---- prologue: stage img chunk 0, prefetch W chunk 0 -----------------------
    {
        float4 v0 = *(const float4*)(imgb + (size_t)kloc * PIXB);
        float4 v1 = *(const float4*)(imgb + (size_t)kloc * PIXB + 4);
        __nv_bfloat162 h0 = __float22bfloat162_rn(make_float2(v0.x, v0.y));
        __nv_bfloat162 h1 = __float22bfloat162_rn(make_float2(v0.z, v0.w));
        __nv_bfloat162 h2 = __float22bfloat162_rn(make_float2(v1.x, v1.y));
        __nv_bfloat162 h3 = __float22bfloat162_rn(make_float2(v1.z, v1.w));
        asm volatile("st.shared.v4.b32 [%0], {%1, %2, %3, %4};"
                     :: "r"(asts), "r"(*(uint32_t*)&h0), "r"(*(uint32_t*)&h1),
                        "r"(*(uint32_t*)&h2), "r"(*(uint32_t*)&h3));
    }
    {
        const char* src = g_Wbf16;
        uint32_t dst = smb + SMG_W;
        #pragma unroll
        for (int j = 0; j < 4; ++j)
            CP_ASYNC16(dst + (t + j * 256) * 16, src + (size_t)(t + j * 256) * 16);
        CP_COMMIT();
    }

    const int wm = warp & 1;    // pixel group (32 rows)
    const int wn = warp >> 1;   // channel group (64 cols)
    float acc[2][8][4];
    #pragma unroll
    for (int i = 0; i < 2; ++i)
        #pragma unroll
        for (int j = 0; j < 8; ++j)
            #pragma unroll
            for (int r = 0; r < 4; ++r) acc[i][j][r] = 0.f;

    // A (trans) lane addressing
    const int krow  = (lane & 7) | ((lane >> 4) << 3);
    const int mhalf = (lane >> 3) & 1;
    const uint32_t ablk0 = ((unsigned)((wm * 32) >> 3) + mhalf) ^ (lane & 7);
    const uint32_t ablk1 = ((unsigned)((wm * 32 + 16) >> 3) + mhalf) ^ (lane & 7);
    const uint32_t abase0 = krow * 128 + (ablk0 << 4);
    const uint32_t abase1 = krow * 128 + (ablk1 << 4);
    // B (W) lane addressing
    const int brow  = wn * 64 + (lane >> 4) * 8 + (lane & 7);
    const int bhalf = (lane >> 3) & 1;

    CP_WAIT_ALL();
    __syncthreads();

    for (int c = 0; c < NCHUNK; ++c) {
        float4 v0, v1;
        if (c + 1 < NCHUNK) {
            // prefetch img chunk c+1 (LDG; consumed after MMA below)
            const float* s = imgb + (size_t)((c + 1) * 32 + kloc) * PIXB;
            v0 = *(const float4*)(s);
            v1 = *(const float4*)(s + 4);
            // prefetch W chunk c+1
            const char* src = g_Wbf16 + (size_t)(c + 1) * W_CHUNK_BYTES;
            uint32_t dst = smb + SMG_W + ((c + 1) & 1) * W_CHUNK_BYTES;
            #pragma unroll
            for (int j = 0; j < 4; ++j)
                CP_ASYNC16(dst + (t + j * 256) * 16, src + (size_t)(t + j * 256) * 16);
            CP_COMMIT();
        }
        const uint32_t abuf = smb + SMG_A + (c & 1) * A_CHUNK_BYTES;
        const uint32_t wbuf = smb + SMG_W + (c & 1) * W_CHUNK_BYTES;

        #pragma unroll
        for (int ks = 0; ks < 2; ++ks) {
            uint32_t a[2][4];
            LDSM_X4_T(a[0][0], a[0][1], a[0][2], a[0][3],
                      abuf + ks * 2048 + abase0);
            LDSM_X4_T(a[1][0], a[1][1], a[1][2], a[1][3],
                      abuf + ks * 2048 + abase1);
            #pragma unroll
            for (int jj = 0; jj < 4; ++jj) {
                uint32_t b0, b1, b2, b3;
                int nrow = brow + jj * 16;
                int kb   = (ks * 2 + bhalf) ^ ((nrow >> 1) & 3);
                LDSM_X4(b0, b1, b2, b3, wbuf + nrow * 64 + (kb << 4));
                mma_bf16(acc[0][2 * jj],     a[0], b0, b1);
                mma_bf16(acc[0][2 * jj + 1], a[0], b2, b3);
                mma_bf16(acc[1][2 * jj],     a[1], b0, b1);
                mma_bf16(acc[1][2 * jj + 1], a[1], b2, b3);
            }
        }

        if (c + 1 < NCHUNK) {
            // convert + store img chunk c+1 into the other A buffer
            __nv_bfloat162 h0 = __float22bfloat162_rn(make_float2(v0.x, v0.y));
            __nv_bfloat162 h1 = __float22bfloat162_rn(make_float2(v0.z, v0.w));
            __nv_bfloat162 h2 = __float22bfloat162_rn(make_float2(v1.x, v1.y));
            __nv_bfloat162 h3 = __float22bfloat162_rn(make_float2(v1.z, v1.w));
            uint32_t dst = asts + (((c + 1) & 1) ? A_CHUNK_BYTES : 0);
            asm volatile("st.shared.v4.b32 [%0], {%1, %2, %3, %4};"
                         :: "r"(dst), "r"(*(uint32_t*)&h0), "r"(*(uint32_t*)&h1),
                            "r"(*(uint32_t*)&h2), "r"(*(uint32_t*)&h3));
        }
        CP_WAIT_ALL();
        __syncthreads();
    }

    // ---- epilogue: G[pixel][col] = acc (fp16) -----------------------------------
    const int cbase = wn * 64 + (lane & 3) * 2;
    const int rbase = p0 + wm * 32 + (lane >> 2);
    #pragma unroll
    for (int i = 0; i < 2; ++i) {
        #pragma unroll
        for (int half = 0; half < 2; ++half) {
            int pix = rbase + i * 16 + half * 8;
            #pragma unroll
            for (int j = 0; j < 8; ++j) {
                int col = cbase + j * 8;
                __half2 h = __floats2half2_rn(acc[i][j][half * 2 + 0],
                                              acc[i][j][half * 2 + 1]);
                *(__half2*)&g_G[(size_t)pix * C_PT + col] = h;
            }
        }
    }
}

// ================== kernel 3: per-point blend + residual ======================
// 1 warp per 2 points (doubled MLP); lane owns 8 channels. G is L2-resident.
__global__ void __launch_bounds__(256)
blend_kernel(const float* __restrict__ point_feat,
             const float* __restrict__ align_b,
             float* __restrict__ out) {
    const int lane = threadIdx.x & 31;
    const int p    = blockIdx.x * 16 + (threadIdx.x >> 5) * 2;
    const int ch   = lane * 8;

    float4 w0 = g_w[p];
    float4 w1 = g_w[p + 1];
    int4   o0 = g_off[p];
    int4   o1 = g_off[p + 1];
    // 8 independent G loads in flight (L2-only; no L1 reuse)
    uint4 a0 = __ldcg((const uint4*)(g_G + o0.x + ch));
    uint4 a1 = __ldcg((const uint4*)(g_G + o0.y + ch));
    uint4 a2 = __ldcg((const uint4*)(g_G + o0.z + ch));
    uint4 a3 = __ldcg((const uint4*)(g_G + o0.w + ch));
    uint4 b0 = __ldcg((const uint4*)(g_G + o1.x + ch));
    uint4 b1 = __ldcg((const uint4*)(g_G + o1.y + ch));
    uint4 b2 = __ldcg((const uint4*)(g_G + o1.z + ch));
    uint4 b3 = __ldcg((const uint4*)(g_G + o1.w + ch));

    float4 bias0 = *(const float4*)&align_b[ch];
    float4 bias1 = *(const float4*)&align_b[ch + 4];

    #pragma unroll
    for (int pt = 0; pt < 2; ++pt) {
        float4 w = pt ? w1 : w0;
        uint4 c0 = pt ? b0 : a0;
        uint4 c1 = pt ? b1 : a1;
        uint4 c2 = pt ? b2 : a2;
        uint4 c3 = pt ? b3 : a3;
        float acc[8];
        #pragma unroll
        for (int k = 0; k < 4; ++k) {
            float2 f0 = __half22float2(((const __half2*)&c0)[k]);
            float2 f1 = __half22float2(((const __half2*)&c1)[k]);
            float2 f2 = __half22float2(((const __half2*)&c2)[k]);
            float2 f3 = __half22float2(((const __half2*)&c3)[k]);
            acc[2*k+0] = w.x * f0.x + w.y * f1.x + w.z * f2.x + w.w * f3.x;
            acc[2*k+1] = w.x * f0.y + w.y * f1.y + w.z * f2.y + w.w * f3.y;
        }
        const int pp = p + pt;
        const float4* pf = (const float4*)&point_feat[(size_t)pp * C_PT + ch];
        float4* op = (float4*)&out[(size_t)pp * C_PT + ch];
        float4 pa = __ldcs(pf);
        float4 pb = __ldcs(pf + 1);
        float4 r0, r1;
        r0.x = pa.x + bias0.x + acc[0];
        r0.y = pa.y + bias0.y + acc[1];
        r0.z = pa.z + bias0.z + acc[2];
        r0.w = pa.w + bias0.w + acc[3];
        r1.x = pb.x + bias1.x + acc[4];
        r1.y = pb.y + bias1.y + acc[5];
        r1.z = pb.z + bias1.z + acc[6];
        r1.w = pb.w + bias1.w + acc[7];
        __stcs(op, r0);
        __stcs(op + 1, r1);
    }
}

// ================== launcher ==================================================
extern "C" void kernel_launch(void* const* d_in, const int* in_sizes, int n_in,
                              void* d_out, int out_size) {
    const float* point_feat = (const float*)d_in[0];
    const float* centers    = (const float*)d_in[1];
    const float* img        = (const float*)d_in[2];
    const float* P2         = (const float*)d_in[3];
    const float* R0         = (const float*)d_in[4];
    const float* Tr         = (const float*)d_in[5];
    const float* align_w    = (const float*)d_in[6];
    const float* align_b    = (const float*)d_in[7];
    const int*   bidx       = (const int*)d_in[8];
    float* out = (float*)d_out;

    // reset tile flags (graph-capturable async memset; no allocation)
    void* flagptr = nullptr;
    cudaGetSymbolAddress(&flagptr, g_tileflag);
    cudaMemsetAsync(flagptr, 0, NTILE * sizeof(int));

    pre_kernel<<<PROJECT_BLOCKS + WCONV_BLOCKS, 256>>>(centers, bidx, P2, R0, Tr,
                                                       align_w);
    cudaFuncSetAttribute(gemm_kernel,
                         cudaFuncAttributeMaxDynamicSharedMemorySize, SMEM_GEMM);
    gemm_kernel<<<NTILE, 256, SMEM_GEMM>>>(img);
    blend_kernel<<<NPTS / 16, 256>>>(point_feat, align_b, out);
}